// round 1
// baseline (speedup 1.0000x reference)
#include <cuda_runtime.h>
#include <cuda_bf16.h>
#include <math.h>

// ---------------------------------------------------------------------------
// Problem constants
// ---------------------------------------------------------------------------
#define BATCH 16
#define SEQ   1024
#define DIM   768
#define HEADS 12
#define HDIM  64
#define HID   3072            // 4*768
#define ROWS  (BATCH*SEQ)     // 16384
#define QKVD  (3*DIM)         // 2304

// ---------------------------------------------------------------------------
// Scratch (device globals — no allocation allowed)
// ---------------------------------------------------------------------------
__device__ float g_ln  [(size_t)ROWS * DIM];   //  50 MB   layernorm output (reused)
__device__ float g_qkv [(size_t)ROWS * QKVD];  // 151 MB   qkv projection
__device__ float g_att [(size_t)ROWS * DIM];   //  50 MB   attention output
__device__ float g_x1  [(size_t)ROWS * DIM];   //  50 MB   x after first residual
__device__ float g_h   [(size_t)ROWS * HID];   // 201 MB   gelu(fc1)

// ---------------------------------------------------------------------------
// LayerNorm: one block per row (D=768), 256 threads, 3 elems/thread
// ---------------------------------------------------------------------------
__global__ void ln_kernel(const float* __restrict__ x,
                          const float* __restrict__ gg,
                          const float* __restrict__ bb,
                          float* __restrict__ y)
{
    const int row = blockIdx.x;
    const int tid = threadIdx.x;
    const float* xr = x + (size_t)row * DIM;

    float v0 = xr[tid], v1 = xr[tid + 256], v2 = xr[tid + 512];
    float s  = v0 + v1 + v2;
    float q  = v0*v0 + v1*v1 + v2*v2;

    #pragma unroll
    for (int m = 16; m; m >>= 1) {
        s += __shfl_xor_sync(0xffffffffu, s, m);
        q += __shfl_xor_sync(0xffffffffu, q, m);
    }
    __shared__ float sh[16];
    const int warp = tid >> 5, lane = tid & 31;
    if (!lane) { sh[warp] = s; sh[warp + 8] = q; }
    __syncthreads();
    if (tid == 0) {
        float ts = 0.f, tq = 0.f;
        #pragma unroll
        for (int w = 0; w < 8; w++) { ts += sh[w]; tq += sh[w + 8]; }
        sh[0] = ts * (1.0f / DIM);
        sh[8] = tq * (1.0f / DIM);
    }
    __syncthreads();
    const float mean = sh[0];
    const float var  = sh[8] - mean * mean;
    const float rstd = rsqrtf(var + 1e-5f);

    float* yr = y + (size_t)row * DIM;
    yr[tid      ] = (v0 - mean) * rstd * gg[tid      ] + bb[tid      ];
    yr[tid + 256] = (v1 - mean) * rstd * gg[tid + 256] + bb[tid + 256];
    yr[tid + 512] = (v2 - mean) * rstd * gg[tid + 512] + bb[tid + 512];
}

// ---------------------------------------------------------------------------
// SGEMM  C[M,N] = A[M,K] * W[N,K]^T + bias  (+ epilogue)
// Tiles: BM=128, BN=64, BK=16, 256 threads, per-thread 8x4.
// EPI: 0 = bias, 1 = bias+GELU(exact), 2 = bias+residual
// ---------------------------------------------------------------------------
template<int EPI>
__global__ void __launch_bounds__(256)
sgemm_kernel(const float* __restrict__ A,
             const float* __restrict__ W,
             const float* __restrict__ bias,
             const float* __restrict__ res,
             float* __restrict__ C,
             int M, int N, int K)
{
    __shared__ float As[16][128];
    __shared__ float Bs[16][64];

    const int tid = threadIdx.x;
    const int ty  = tid >> 4;          // 0..15 -> 8 rows each
    const int tx  = tid & 15;          // 0..15 -> 4 cols each
    const int m0  = blockIdx.y * 128;
    const int n0  = blockIdx.x * 64;

    const int arow = tid >> 1, acol = (tid & 1) * 8;   // A tile loader
    const int brow = tid >> 2, bcol = (tid & 3) * 4;   // W tile loader

    float acc[8][4];
    #pragma unroll
    for (int i = 0; i < 8; i++)
        #pragma unroll
        for (int j = 0; j < 4; j++) acc[i][j] = 0.f;

    const float* ap = A + (size_t)(m0 + arow) * K + acol;
    const float* bp = W + (size_t)(n0 + brow) * K + bcol;

    for (int k0 = 0; k0 < K; k0 += 16) {
        float4 a0 = *(const float4*)(ap + k0);
        float4 a1 = *(const float4*)(ap + k0 + 4);
        float4 bv = *(const float4*)(bp + k0);

        __syncthreads();   // previous compute done before smem overwrite
        As[acol + 0][arow] = a0.x;  As[acol + 1][arow] = a0.y;
        As[acol + 2][arow] = a0.z;  As[acol + 3][arow] = a0.w;
        As[acol + 4][arow] = a1.x;  As[acol + 5][arow] = a1.y;
        As[acol + 6][arow] = a1.z;  As[acol + 7][arow] = a1.w;
        Bs[bcol + 0][brow] = bv.x;  Bs[bcol + 1][brow] = bv.y;
        Bs[bcol + 2][brow] = bv.z;  Bs[bcol + 3][brow] = bv.w;
        __syncthreads();

        #pragma unroll
        for (int kk = 0; kk < 16; kk++) {
            float4 aA = *(const float4*)&As[kk][ty * 8];
            float4 aB = *(const float4*)&As[kk][ty * 8 + 4];
            float4 b4 = *(const float4*)&Bs[kk][tx * 4];
            float a[8] = {aA.x, aA.y, aA.z, aA.w, aB.x, aB.y, aB.z, aB.w};
            float b[4] = {b4.x, b4.y, b4.z, b4.w};
            #pragma unroll
            for (int i = 0; i < 8; i++)
                #pragma unroll
                for (int j = 0; j < 4; j++)
                    acc[i][j] = fmaf(a[i], b[j], acc[i][j]);
        }
    }

    float bz[4];
    #pragma unroll
    for (int j = 0; j < 4; j++) bz[j] = bias[n0 + tx * 4 + j];

    #pragma unroll
    for (int i = 0; i < 8; i++) {
        const int m = m0 + ty * 8 + i;
        float o[4];
        #pragma unroll
        for (int j = 0; j < 4; j++) {
            float v = acc[i][j] + bz[j];
            if (EPI == 1) v = 0.5f * v * (1.0f + erff(v * 0.70710678118654752f));
            if (EPI == 2) v += res[(size_t)m * N + n0 + tx * 4 + j];
            o[j] = v;
        }
        *(float4*)(C + (size_t)m * N + n0 + tx * 4) =
            make_float4(o[0], o[1], o[2], o[3]);
    }
}

// ---------------------------------------------------------------------------
// Fused attention (flash-style, fp32). One block per (q-tile 64, head, batch).
// scores = Q K^T / sqrt(768)  (reference scales by full model dim!)
// ---------------------------------------------------------------------------
__global__ void __launch_bounds__(256)
attn_kernel(const float* __restrict__ qkv, float* __restrict__ out)
{
    __shared__ float Qt[64][64];   // [d][r], pre-scaled
    __shared__ float KV[64][64];   // K phase: [d][c]; V phase: [c][d]
    __shared__ float Ps[64][64];   // probabilities [r][c]

    const int b  = blockIdx.z;
    const int h  = blockIdx.y;
    const int q0 = blockIdx.x * 64;

    const int tid = threadIdx.x;
    const int ty  = tid >> 4;      // 0..15 -> 4 q-rows each
    const int tx  = tid & 15;      // 0..15 -> 4 cols each

    const int lr = tid >> 2;            // loader row 0..63
    const int lc = (tid & 3) * 16;      // loader col group

    const float scale = 0.03608439182435161f;   // 1/sqrt(768)
    const size_t rowstride = QKVD;

    // ---- load Q tile (pre-scaled), layout [d][r] ----
    {
        const float* qp = qkv + ((size_t)(b * SEQ + q0 + lr)) * rowstride + h * HDIM + lc;
        #pragma unroll
        for (int g = 0; g < 4; g++) {
            float4 v = *(const float4*)(qp + g * 4);
            Qt[lc + g * 4 + 0][lr] = v.x * scale;
            Qt[lc + g * 4 + 1][lr] = v.y * scale;
            Qt[lc + g * 4 + 2][lr] = v.z * scale;
            Qt[lc + g * 4 + 3][lr] = v.w * scale;
        }
    }
    __syncthreads();

    float m_i[4], l_i[4], o[4][4];
    #pragma unroll
    for (int i = 0; i < 4; i++) {
        m_i[i] = -1e30f; l_i[i] = 0.f;
        #pragma unroll
        for (int j = 0; j < 4; j++) o[i][j] = 0.f;
    }

    for (int t = 0; t < SEQ / 64; t++) {
        const size_t srow = (size_t)(b * SEQ + t * 64 + lr) * rowstride + h * HDIM + lc;
        // prefetch K tile to regs
        float4 kr[4];
        {
            const float* kp = qkv + srow + DIM;      // K block
            #pragma unroll
            for (int g = 0; g < 4; g++) kr[g] = *(const float4*)(kp + g * 4);
        }
        __syncthreads();   // prior iteration done reading KV(V) / Ps
        #pragma unroll
        for (int g = 0; g < 4; g++) {               // K stored transposed [d][c]
            KV[lc + g * 4 + 0][lr] = kr[g].x;
            KV[lc + g * 4 + 1][lr] = kr[g].y;
            KV[lc + g * 4 + 2][lr] = kr[g].z;
            KV[lc + g * 4 + 3][lr] = kr[g].w;
        }
        __syncthreads();

        // ---- scores S = Q K^T (4x4 per thread) ----
        float s[4][4];
        #pragma unroll
        for (int i = 0; i < 4; i++)
            #pragma unroll
            for (int j = 0; j < 4; j++) s[i][j] = 0.f;
        #pragma unroll 8
        for (int d = 0; d < 64; d++) {
            float4 qa = *(const float4*)&Qt[d][ty * 4];
            float4 kb = *(const float4*)&KV[d][tx * 4];
            float a[4] = {qa.x, qa.y, qa.z, qa.w};
            float k4[4] = {kb.x, kb.y, kb.z, kb.w};
            #pragma unroll
            for (int i = 0; i < 4; i++)
                #pragma unroll
                for (int j = 0; j < 4; j++)
                    s[i][j] = fmaf(a[i], k4[j], s[i][j]);
        }

        // ---- online softmax ----
        float p[4][4], rs[4];
        #pragma unroll
        for (int i = 0; i < 4; i++) {
            float rm = fmaxf(fmaxf(s[i][0], s[i][1]), fmaxf(s[i][2], s[i][3]));
            #pragma unroll
            for (int mk = 8; mk; mk >>= 1)
                rm = fmaxf(rm, __shfl_xor_sync(0xffffffffu, rm, mk));
            const float mn    = fmaxf(m_i[i], rm);
            const float alpha = __expf(m_i[i] - mn);
            float sum = 0.f;
            #pragma unroll
            for (int j = 0; j < 4; j++) { p[i][j] = __expf(s[i][j] - mn); sum += p[i][j]; }
            #pragma unroll
            for (int mk = 8; mk; mk >>= 1)
                sum += __shfl_xor_sync(0xffffffffu, sum, mk);
            l_i[i] = l_i[i] * alpha + sum;
            m_i[i] = mn;
            #pragma unroll
            for (int j = 0; j < 4; j++) o[i][j] *= alpha;
            rs[i] = sum; (void)rs;
        }

        // prefetch V tile to regs
        float4 vr[4];
        {
            const float* vp = qkv + srow + 2 * DIM;  // V block
            #pragma unroll
            for (int g = 0; g < 4; g++) vr[g] = *(const float4*)(vp + g * 4);
        }
        __syncthreads();   // everyone done reading KV(K)
        #pragma unroll
        for (int g = 0; g < 4; g++)                  // V stored row-major [c][d]
            *(float4*)&KV[lr][lc + g * 4] = vr[g];
        #pragma unroll
        for (int i = 0; i < 4; i++)
            *(float4*)&Ps[ty * 4 + i][tx * 4] = make_float4(p[i][0], p[i][1], p[i][2], p[i][3]);
        __syncthreads();

        // ---- O += P V ----
        #pragma unroll 8
        for (int c = 0; c < 64; c++) {
            float4 vv = *(const float4*)&KV[c][tx * 4];
            float v4[4] = {vv.x, vv.y, vv.z, vv.w};
            #pragma unroll
            for (int i = 0; i < 4; i++) {
                float pv = Ps[ty * 4 + i][c];
                #pragma unroll
                for (int j = 0; j < 4; j++)
                    o[i][j] = fmaf(pv, v4[j], o[i][j]);
            }
        }
    }

    // ---- normalize + store ----
    #pragma unroll
    for (int i = 0; i < 4; i++) {
        const float inv = 1.0f / l_i[i];
        float* op = out + (size_t)(b * SEQ + q0 + ty * 4 + i) * DIM + h * HDIM + tx * 4;
        *(float4*)op = make_float4(o[i][0] * inv, o[i][1] * inv, o[i][2] * inv, o[i][3] * inv);
    }
}

// ---------------------------------------------------------------------------
// Host entry
// ---------------------------------------------------------------------------
extern "C" void kernel_launch(void* const* d_in, const int* in_sizes, int n_in,
                              void* d_out, int out_size)
{
    const float* x     = (const float*)d_in[0];
    const float* ln_g  = (const float*)d_in[1];
    const float* ln_b  = (const float*)d_in[2];
    const float* w_qkv = (const float*)d_in[3];
    const float* b_qkv = (const float*)d_in[4];
    const float* w_out = (const float*)d_in[5];
    const float* b_out = (const float*)d_in[6];
    const float* w_fc1 = (const float*)d_in[7];
    const float* b_fc1 = (const float*)d_in[8];
    const float* w_fc2 = (const float*)d_in[9];
    const float* b_fc2 = (const float*)d_in[10];
    float* out = (float*)d_out;

    float *p_ln, *p_qkv, *p_att, *p_x1, *p_h;
    cudaGetSymbolAddress((void**)&p_ln,  g_ln);
    cudaGetSymbolAddress((void**)&p_qkv, g_qkv);
    cudaGetSymbolAddress((void**)&p_att, g_att);
    cudaGetSymbolAddress((void**)&p_x1,  g_x1);
    cudaGetSymbolAddress((void**)&p_h,   g_h);

    // 1) ln1 = LN(x)
    ln_kernel<<<ROWS, 256>>>(x, ln_g, ln_b, p_ln);

    // 2) qkv = ln1 @ w_qkv^T + b_qkv
    sgemm_kernel<0><<<dim3(QKVD / 64, ROWS / 128), 256>>>(
        p_ln, w_qkv, b_qkv, nullptr, p_qkv, ROWS, QKVD, DIM);

    // 3) fused attention
    attn_kernel<<<dim3(SEQ / 64, HEADS, BATCH), 256>>>(p_qkv, p_att);

    // 4) x1 = x + att @ w_out^T + b_out
    sgemm_kernel<2><<<dim3(DIM / 64, ROWS / 128), 256>>>(
        p_att, w_out, b_out, x, p_x1, ROWS, DIM, DIM);

    // 5) ln2 = LN(x1)
    ln_kernel<<<ROWS, 256>>>(p_x1, ln_g, ln_b, p_ln);

    // 6) h = gelu(ln2 @ w_fc1^T + b_fc1)
    sgemm_kernel<1><<<dim3(HID / 64, ROWS / 128), 256>>>(
        p_ln, w_fc1, b_fc1, nullptr, p_h, ROWS, HID, DIM);

    // 7) out = x1 + h @ w_fc2^T + b_fc2
    sgemm_kernel<2><<<dim3(DIM / 64, ROWS / 128), 256>>>(
        p_h, w_fc2, b_fc2, p_x1, out, ROWS, DIM, HID);
}

// round 3
// speedup vs baseline: 1.8317x; 1.8317x over previous
#include <cuda_runtime.h>
#include <cuda_bf16.h>
#include <cstdint>
#include <math.h>

// ---------------------------------------------------------------------------
// Problem constants
// ---------------------------------------------------------------------------
#define BATCH 16
#define SEQ   1024
#define DIM   768
#define HEADS 12
#define HDIM  64
#define HID   3072
#define ROWS  (BATCH*SEQ)     // 16384
#define QKVD  (3*DIM)         // 2304

// ---------------------------------------------------------------------------
// Scratch (device globals — no allocation allowed)
// ---------------------------------------------------------------------------
__device__ float g_ln  [(size_t)ROWS * DIM];
__device__ float g_qkv [(size_t)ROWS * QKVD];
__device__ float g_att [(size_t)ROWS * DIM];
__device__ float g_x1  [(size_t)ROWS * DIM];
__device__ float g_h   [(size_t)ROWS * HID];

// ---------------------------------------------------------------------------
// Helpers
// ---------------------------------------------------------------------------
__device__ __forceinline__ uint32_t smem_u32(const void* p) {
    uint32_t a;
    asm("{ .reg .u64 t; cvta.to.shared.u64 t, %1; cvt.u32.u64 %0, t; }" : "=r"(a) : "l"(p));
    return a;
}
__device__ __forceinline__ uint32_t f2tf32(float f) {
    uint32_t r;
    asm("cvt.rna.tf32.f32 %0, %1;" : "=r"(r) : "f"(f));
    return r;
}
__device__ __forceinline__ void ldsm4(uint32_t* r, uint32_t addr) {
    asm volatile("ldmatrix.sync.aligned.m8n8.x4.shared.b16 {%0,%1,%2,%3}, [%4];"
        : "=r"(r[0]), "=r"(r[1]), "=r"(r[2]), "=r"(r[3]) : "r"(addr));
}
__device__ __forceinline__ void mma_tf32(float* c, const uint32_t* a,
                                         uint32_t b0, uint32_t b1) {
    asm volatile(
        "mma.sync.aligned.m16n8k8.row.col.f32.tf32.tf32.f32 "
        "{%0,%1,%2,%3}, {%4,%5,%6,%7}, {%8,%9}, {%0,%1,%2,%3};"
        : "+f"(c[0]), "+f"(c[1]), "+f"(c[2]), "+f"(c[3])
        : "r"(a[0]), "r"(a[1]), "r"(a[2]), "r"(a[3]), "r"(b0), "r"(b1));
}
__device__ __forceinline__ uint32_t sw128(uint32_t off) {
    return off ^ ((off >> 3) & 0x70);
}

// ---------------------------------------------------------------------------
// LayerNorm: one block per row (D=768), 256 threads
// ---------------------------------------------------------------------------
__global__ void ln_kernel(const float* __restrict__ x,
                          const float* __restrict__ gg,
                          const float* __restrict__ bb,
                          float* __restrict__ y)
{
    const int row = blockIdx.x;
    const int tid = threadIdx.x;
    const float* xr = x + (size_t)row * DIM;

    float v0 = xr[tid], v1 = xr[tid + 256], v2 = xr[tid + 512];
    float s  = v0 + v1 + v2;
    float q  = v0*v0 + v1*v1 + v2*v2;

    #pragma unroll
    for (int m = 16; m; m >>= 1) {
        s += __shfl_xor_sync(0xffffffffu, s, m);
        q += __shfl_xor_sync(0xffffffffu, q, m);
    }
    __shared__ float sh[16];
    const int warp = tid >> 5, lane = tid & 31;
    if (!lane) { sh[warp] = s; sh[warp + 8] = q; }
    __syncthreads();
    if (tid == 0) {
        float ts = 0.f, tq = 0.f;
        #pragma unroll
        for (int w = 0; w < 8; w++) { ts += sh[w]; tq += sh[w + 8]; }
        sh[0] = ts * (1.0f / DIM);
        sh[8] = tq * (1.0f / DIM);
    }
    __syncthreads();
    const float mean = sh[0];
    const float var  = sh[8] - mean * mean;
    const float rstd = rsqrtf(var + 1e-5f);

    float* yr = y + (size_t)row * DIM;
    yr[tid      ] = (v0 - mean) * rstd * gg[tid      ] + bb[tid      ];
    yr[tid + 256] = (v1 - mean) * rstd * gg[tid + 256] + bb[tid + 256];
    yr[tid + 512] = (v2 - mean) * rstd * gg[tid + 512] + bb[tid + 512];
}

// ---------------------------------------------------------------------------
// tf32 mma.sync GEMM:  C[M,N] = A[M,K] @ W[N,K]^T + bias (+ epilogue)
// Tile 128x128, BK=32, 256 threads (8 warps, 4x2), warp tile 32x64.
// SMEM: A0@0, B0@16K, A1@32K, B1@48K (SW128 swizzled, K-major 128B rows).
// EPI: 0 = bias, 1 = bias+GELU(exact), 2 = bias+residual
// ---------------------------------------------------------------------------
template<int EPI>
__global__ void __launch_bounds__(256, 1)
tgemm_kernel(const float* __restrict__ A,
             const float* __restrict__ W,
             const float* __restrict__ bias,
             const float* __restrict__ res,
             float* __restrict__ C,
             int M, int N, int K)
{
    extern __shared__ char smem[];
    const uint32_t sb = smem_u32(smem);
    const int tid   = threadIdx.x;
    const int wid   = tid >> 5;
    const int lane  = tid & 31;
    const int warpM = wid & 3;          // 0..3  -> 32-row slice
    const int warpN = wid >> 2;         // 0..1  -> 64-col slice
    const int m0 = blockIdx.y * 128;
    const int n0 = blockIdx.x * 128;

    // ldmatrix lane offsets (within a 128x32f tile, swizzled), ks=0
    uint32_t aOff[2], bOff[4];
    {
        const int r8 = (lane & 7) + ((lane >> 3) & 1) * 8;
        #pragma unroll
        for (int mf = 0; mf < 2; mf++) {
            const int row = warpM * 32 + mf * 16 + r8;
            aOff[mf] = sw128((uint32_t)(row * 128 + (lane >> 4) * 16));
        }
        const int rB = (lane & 7) + ((lane >> 4) & 1) * 8;
        #pragma unroll
        for (int p = 0; p < 4; p++) {
            const int row = warpN * 64 + p * 16 + rB;
            bOff[p] = sw128((uint32_t)(row * 128 + ((lane >> 3) & 1) * 16));
        }
    }

    float acc[2][8][4];
    #pragma unroll
    for (int i = 0; i < 2; i++)
        #pragma unroll
        for (int j = 0; j < 8; j++)
            #pragma unroll
            for (int q = 0; q < 4; q++) acc[i][j][q] = 0.f;

    const int nIter = K >> 5;
    const int lrow  = tid >> 3;          // 0..127 (loads 1 row, 2 tiles: A,B)
    const int lch   = tid & 7;           // 16B chunk within row
    const uint32_t stOff = sw128((uint32_t)(lrow * 128 + lch * 16));
    const float* apt = A + (size_t)(m0 + lrow) * K + lch * 4;
    const float* bpt = W + (size_t)(n0 + lrow) * K + lch * 4;

    // each thread loads 4 rows-strided-32 groups? No: 1024 float4 per tile,
    // 256 threads -> 4 groups spaced 32 rows apart.
    uint4 va[4], vb[4];
    #pragma unroll
    for (int g = 0; g < 4; g++) {
        float4 a = *(const float4*)(apt + (size_t)g * 32 * K);
        float4 b = *(const float4*)(bpt + (size_t)g * 32 * K);
        va[g] = make_uint4(f2tf32(a.x), f2tf32(a.y), f2tf32(a.z), f2tf32(a.w));
        vb[g] = make_uint4(f2tf32(b.x), f2tf32(b.y), f2tf32(b.z), f2tf32(b.w));
    }
    #pragma unroll
    for (int g = 0; g < 4; g++) {
        *(uint4*)(smem +         stOff + g * 32 * 128) = va[g];
        *(uint4*)(smem + 16384 + stOff + g * 32 * 128) = vb[g];
    }
    __syncthreads();

    for (int it = 0; it < nIter; ++it) {
        const uint32_t aB = sb + (uint32_t)((it & 1) ? 32768 : 0);
        const uint32_t bB = aB + 16384;

        if (it + 1 < nIter) {
            const int k0 = (it + 1) << 5;
            #pragma unroll
            for (int g = 0; g < 4; g++) {
                float4 a = *(const float4*)(apt + (size_t)g * 32 * K + k0);
                float4 b = *(const float4*)(bpt + (size_t)g * 32 * K + k0);
                va[g] = make_uint4(f2tf32(a.x), f2tf32(a.y), f2tf32(a.z), f2tf32(a.w));
                vb[g] = make_uint4(f2tf32(b.x), f2tf32(b.y), f2tf32(b.z), f2tf32(b.w));
            }
        }

        #pragma unroll
        for (int ks = 0; ks < 4; ks++) {
            const uint32_t kx = (uint32_t)(ks << 5);
            uint32_t af[2][4], bf[4][4];
            #pragma unroll
            for (int mf = 0; mf < 2; mf++) ldsm4(af[mf], aB + (aOff[mf] ^ kx));
            #pragma unroll
            for (int p = 0; p < 4; p++)   ldsm4(bf[p],  bB + (bOff[p]  ^ kx));
            #pragma unroll
            for (int mf = 0; mf < 2; mf++)
                #pragma unroll
                for (int nf = 0; nf < 8; nf++)
                    mma_tf32(acc[mf][nf], af[mf],
                             bf[nf >> 1][(nf & 1) * 2],
                             bf[nf >> 1][(nf & 1) * 2 + 1]);
        }

        if (it + 1 < nIter) {
            const uint32_t base = (uint32_t)((it & 1) ? 0 : 32768);
            #pragma unroll
            for (int g = 0; g < 4; g++) {
                *(uint4*)(smem + base +         stOff + g * 32 * 128) = va[g];
                *(uint4*)(smem + base + 16384 + stOff + g * 32 * 128) = vb[g];
            }
            __syncthreads();
        }
    }

    // epilogue
    #pragma unroll
    for (int mf = 0; mf < 2; mf++) {
        const int r0 = m0 + warpM * 32 + mf * 16 + (lane >> 2);
        #pragma unroll
        for (int nf = 0; nf < 8; nf++) {
            const int col = n0 + warpN * 64 + nf * 8 + (lane & 3) * 2;
            const float b0 = bias[col], b1 = bias[col + 1];
            #pragma unroll
            for (int h = 0; h < 2; h++) {
                const int r = r0 + h * 8;
                float v0 = acc[mf][nf][h * 2 + 0] + b0;
                float v1 = acc[mf][nf][h * 2 + 1] + b1;
                if (EPI == 1) {
                    v0 = 0.5f * v0 * (1.0f + erff(v0 * 0.70710678118654752f));
                    v1 = 0.5f * v1 * (1.0f + erff(v1 * 0.70710678118654752f));
                }
                if (EPI == 2) {
                    const float2 rr = *(const float2*)(res + (size_t)r * N + col);
                    v0 += rr.x; v1 += rr.y;
                }
                *(float2*)(C + (size_t)r * N + col) = make_float2(v0, v1);
            }
        }
    }
}

// ---------------------------------------------------------------------------
// Fused attention (flash-style, fp32) — unchanged (passing, ~0.9ms)
// ---------------------------------------------------------------------------
__global__ void __launch_bounds__(256)
attn_kernel(const float* __restrict__ qkv, float* __restrict__ out)
{
    __shared__ float Qt[64][64];
    __shared__ float KV[64][64];
    __shared__ float Ps[64][64];

    const int b  = blockIdx.z;
    const int h  = blockIdx.y;
    const int q0 = blockIdx.x * 64;

    const int tid = threadIdx.x;
    const int ty  = tid >> 4;
    const int tx  = tid & 15;

    const int lr = tid >> 2;
    const int lc = (tid & 3) * 16;

    const float scale = 0.03608439182435161f;   // 1/sqrt(768)
    const size_t rowstride = QKVD;

    {
        const float* qp = qkv + ((size_t)(b * SEQ + q0 + lr)) * rowstride + h * HDIM + lc;
        #pragma unroll
        for (int g = 0; g < 4; g++) {
            float4 v = *(const float4*)(qp + g * 4);
            Qt[lc + g * 4 + 0][lr] = v.x * scale;
            Qt[lc + g * 4 + 1][lr] = v.y * scale;
            Qt[lc + g * 4 + 2][lr] = v.z * scale;
            Qt[lc + g * 4 + 3][lr] = v.w * scale;
        }
    }
    __syncthreads();

    float m_i[4], l_i[4], o[4][4];
    #pragma unroll
    for (int i = 0; i < 4; i++) {
        m_i[i] = -1e30f; l_i[i] = 0.f;
        #pragma unroll
        for (int j = 0; j < 4; j++) o[i][j] = 0.f;
    }

    for (int t = 0; t < SEQ / 64; t++) {
        const size_t srow = (size_t)(b * SEQ + t * 64 + lr) * rowstride + h * HDIM + lc;
        float4 kr[4];
        {
            const float* kp = qkv + srow + DIM;
            #pragma unroll
            for (int g = 0; g < 4; g++) kr[g] = *(const float4*)(kp + g * 4);
        }
        __syncthreads();
        #pragma unroll
        for (int g = 0; g < 4; g++) {
            KV[lc + g * 4 + 0][lr] = kr[g].x;
            KV[lc + g * 4 + 1][lr] = kr[g].y;
            KV[lc + g * 4 + 2][lr] = kr[g].z;
            KV[lc + g * 4 + 3][lr] = kr[g].w;
        }
        __syncthreads();

        float s[4][4];
        #pragma unroll
        for (int i = 0; i < 4; i++)
            #pragma unroll
            for (int j = 0; j < 4; j++) s[i][j] = 0.f;
        #pragma unroll 8
        for (int d = 0; d < 64; d++) {
            float4 qa = *(const float4*)&Qt[d][ty * 4];
            float4 kb = *(const float4*)&KV[d][tx * 4];
            float a[4] = {qa.x, qa.y, qa.z, qa.w};
            float k4[4] = {kb.x, kb.y, kb.z, kb.w};
            #pragma unroll
            for (int i = 0; i < 4; i++)
                #pragma unroll
                for (int j = 0; j < 4; j++)
                    s[i][j] = fmaf(a[i], k4[j], s[i][j]);
        }

        float p[4][4];
        #pragma unroll
        for (int i = 0; i < 4; i++) {
            float rm = fmaxf(fmaxf(s[i][0], s[i][1]), fmaxf(s[i][2], s[i][3]));
            #pragma unroll
            for (int mk = 8; mk; mk >>= 1)
                rm = fmaxf(rm, __shfl_xor_sync(0xffffffffu, rm, mk));
            const float mn    = fmaxf(m_i[i], rm);
            const float alpha = __expf(m_i[i] - mn);
            float sum = 0.f;
            #pragma unroll
            for (int j = 0; j < 4; j++) { p[i][j] = __expf(s[i][j] - mn); sum += p[i][j]; }
            #pragma unroll
            for (int mk = 8; mk; mk >>= 1)
                sum += __shfl_xor_sync(0xffffffffu, sum, mk);
            l_i[i] = l_i[i] * alpha + sum;
            m_i[i] = mn;
            #pragma unroll
            for (int j = 0; j < 4; j++) o[i][j] *= alpha;
        }

        float4 vr[4];
        {
            const float* vp = qkv + srow + 2 * DIM;
            #pragma unroll
            for (int g = 0; g < 4; g++) vr[g] = *(const float4*)(vp + g * 4);
        }
        __syncthreads();
        #pragma unroll
        for (int g = 0; g < 4; g++)
            *(float4*)&KV[lr][lc + g * 4] = vr[g];
        #pragma unroll
        for (int i = 0; i < 4; i++)
            *(float4*)&Ps[ty * 4 + i][tx * 4] = make_float4(p[i][0], p[i][1], p[i][2], p[i][3]);
        __syncthreads();

        #pragma unroll 8
        for (int c = 0; c < 64; c++) {
            float4 vv = *(const float4*)&KV[c][tx * 4];
            float v4[4] = {vv.x, vv.y, vv.z, vv.w};
            #pragma unroll
            for (int i = 0; i < 4; i++) {
                float pv = Ps[ty * 4 + i][c];
                #pragma unroll
                for (int j = 0; j < 4; j++)
                    o[i][j] = fmaf(pv, v4[j], o[i][j]);
            }
        }
    }

    #pragma unroll
    for (int i = 0; i < 4; i++) {
        const float inv = 1.0f / l_i[i];
        float* op = out + (size_t)(b * SEQ + q0 + ty * 4 + i) * DIM + h * HDIM + tx * 4;
        *(float4*)op = make_float4(o[i][0] * inv, o[i][1] * inv, o[i][2] * inv, o[i][3] * inv);
    }
}

// ---------------------------------------------------------------------------
// Host entry
// ---------------------------------------------------------------------------
extern "C" void kernel_launch(void* const* d_in, const int* in_sizes, int n_in,
                              void* d_out, int out_size)
{
    const float* x     = (const float*)d_in[0];
    const float* ln_g  = (const float*)d_in[1];
    const float* ln_b  = (const float*)d_in[2];
    const float* w_qkv = (const float*)d_in[3];
    const float* b_qkv = (const float*)d_in[4];
    const float* w_out = (const float*)d_in[5];
    const float* b_out = (const float*)d_in[6];
    const float* w_fc1 = (const float*)d_in[7];
    const float* b_fc1 = (const float*)d_in[8];
    const float* w_fc2 = (const float*)d_in[9];
    const float* b_fc2 = (const float*)d_in[10];
    float* out = (float*)d_out;

    float *p_ln, *p_qkv, *p_att, *p_x1, *p_h;
    cudaGetSymbolAddress((void**)&p_ln,  g_ln);
    cudaGetSymbolAddress((void**)&p_qkv, g_qkv);
    cudaGetSymbolAddress((void**)&p_att, g_att);
    cudaGetSymbolAddress((void**)&p_x1,  g_x1);
    cudaGetSymbolAddress((void**)&p_h,   g_h);

    const int SMEM_BYTES = 65536;
    static bool attr_set = false;
    if (!attr_set) {
        cudaFuncSetAttribute(tgemm_kernel<0>,
            cudaFuncAttributeMaxDynamicSharedMemorySize, SMEM_BYTES);
        cudaFuncSetAttribute(tgemm_kernel<1>,
            cudaFuncAttributeMaxDynamicSharedMemorySize, SMEM_BYTES);
        cudaFuncSetAttribute(tgemm_kernel<2>,
            cudaFuncAttributeMaxDynamicSharedMemorySize, SMEM_BYTES);
        attr_set = true;
    }

    // 1) ln1 = LN(x)
    ln_kernel<<<ROWS, 256>>>(x, ln_g, ln_b, p_ln);

    // 2) qkv = ln1 @ w_qkv^T + b_qkv
    tgemm_kernel<0><<<dim3(QKVD / 128, ROWS / 128), 256, SMEM_BYTES>>>(
        p_ln, w_qkv, b_qkv, nullptr, p_qkv, ROWS, QKVD, DIM);

    // 3) fused attention
    attn_kernel<<<dim3(SEQ / 64, HEADS, BATCH), 256>>>(p_qkv, p_att);

    // 4) x1 = x + att @ w_out^T + b_out
    tgemm_kernel<2><<<dim3(DIM / 128, ROWS / 128), 256, SMEM_BYTES>>>(
        p_att, w_out, b_out, x, p_x1, ROWS, DIM, DIM);

    // 5) ln2 = LN(x1)
    ln_kernel<<<ROWS, 256>>>(p_x1, ln_g, ln_b, p_ln);

    // 6) h = gelu(ln2 @ w_fc1^T + b_fc1)
    tgemm_kernel<1><<<dim3(HID / 128, ROWS / 128), 256, SMEM_BYTES>>>(
        p_ln, w_fc1, b_fc1, nullptr, p_h, ROWS, HID, DIM);

    // 7) out = x1 + h @ w_fc2^T + b_fc2
    tgemm_kernel<2><<<dim3(DIM / 128, ROWS / 128), 256, SMEM_BYTES>>>(
        p_h, w_fc2, b_fc2, p_x1, out, ROWS, DIM, HID);
}

// round 4
// speedup vs baseline: 2.5152x; 1.3732x over previous
#include <cuda_runtime.h>
#include <cuda_bf16.h>
#include <cstdint>
#include <math.h>

// ---------------------------------------------------------------------------
// Problem constants
// ---------------------------------------------------------------------------
#define BATCH 16
#define SEQ   1024
#define DIM   768
#define HEADS 12
#define HDIM  64
#define HID   3072
#define ROWS  (BATCH*SEQ)     // 16384
#define QKVD  (3*DIM)         // 2304

// ---------------------------------------------------------------------------
// Scratch (device globals — no allocation allowed)
// ---------------------------------------------------------------------------
__device__ float g_ln  [(size_t)ROWS * DIM];
__device__ float g_qkv [(size_t)ROWS * QKVD];
__device__ float g_att [(size_t)ROWS * DIM];
__device__ float g_x1  [(size_t)ROWS * DIM];
__device__ float g_h   [(size_t)ROWS * HID];

// ---------------------------------------------------------------------------
// Helpers
// ---------------------------------------------------------------------------
__device__ __forceinline__ uint32_t smem_u32(const void* p) {
    uint32_t a;
    asm("{ .reg .u64 t; cvta.to.shared.u64 t, %1; cvt.u32.u64 %0, t; }" : "=r"(a) : "l"(p));
    return a;
}
__device__ __forceinline__ void ldsm4(uint32_t* r, uint32_t addr) {
    asm volatile("ldmatrix.sync.aligned.m8n8.x4.shared.b16 {%0,%1,%2,%3}, [%4];"
        : "=r"(r[0]), "=r"(r[1]), "=r"(r[2]), "=r"(r[3]) : "r"(addr));
}
__device__ __forceinline__ void mma_tf32(float* c, const uint32_t* a,
                                         uint32_t b0, uint32_t b1) {
    asm volatile(
        "mma.sync.aligned.m16n8k8.row.col.f32.tf32.tf32.f32 "
        "{%0,%1,%2,%3}, {%4,%5,%6,%7}, {%8,%9}, {%0,%1,%2,%3};"
        : "+f"(c[0]), "+f"(c[1]), "+f"(c[2]), "+f"(c[3])
        : "r"(a[0]), "r"(a[1]), "r"(a[2]), "r"(a[3]), "r"(b0), "r"(b1));
}
__device__ __forceinline__ uint32_t sw128(uint32_t off) {
    return off ^ ((off >> 3) & 0x70);
}
#define CP_ASYNC16(dst, src) \
    asm volatile("cp.async.cg.shared.global [%0], [%1], 16;" \
                 :: "r"(dst), "l"(src) : "memory")
#define CP_COMMIT() asm volatile("cp.async.commit_group;" ::: "memory")
#define CP_WAIT1()  asm volatile("cp.async.wait_group 1;"  ::: "memory")

// ---------------------------------------------------------------------------
// LayerNorm: one block per row (D=768), 256 threads
// ---------------------------------------------------------------------------
__global__ void ln_kernel(const float* __restrict__ x,
                          const float* __restrict__ gg,
                          const float* __restrict__ bb,
                          float* __restrict__ y)
{
    const int row = blockIdx.x;
    const int tid = threadIdx.x;
    const float* xr = x + (size_t)row * DIM;

    float v0 = xr[tid], v1 = xr[tid + 256], v2 = xr[tid + 512];
    float s  = v0 + v1 + v2;
    float q  = v0*v0 + v1*v1 + v2*v2;

    #pragma unroll
    for (int m = 16; m; m >>= 1) {
        s += __shfl_xor_sync(0xffffffffu, s, m);
        q += __shfl_xor_sync(0xffffffffu, q, m);
    }
    __shared__ float sh[16];
    const int warp = tid >> 5, lane = tid & 31;
    if (!lane) { sh[warp] = s; sh[warp + 8] = q; }
    __syncthreads();
    if (tid == 0) {
        float ts = 0.f, tq = 0.f;
        #pragma unroll
        for (int w = 0; w < 8; w++) { ts += sh[w]; tq += sh[w + 8]; }
        sh[0] = ts * (1.0f / DIM);
        sh[8] = tq * (1.0f / DIM);
    }
    __syncthreads();
    const float mean = sh[0];
    const float var  = sh[8] - mean * mean;
    const float rstd = rsqrtf(var + 1e-5f);

    float* yr = y + (size_t)row * DIM;
    yr[tid      ] = (v0 - mean) * rstd * gg[tid      ] + bb[tid      ];
    yr[tid + 256] = (v1 - mean) * rstd * gg[tid + 256] + bb[tid + 256];
    yr[tid + 512] = (v2 - mean) * rstd * gg[tid + 512] + bb[tid + 512];
}

// ---------------------------------------------------------------------------
// tf32 mma.sync GEMM, cp.async 3-stage pipeline.
// C[M,N] = A[M,K] @ W[N,K]^T + bias (+ epilogue)
// Tile 128x128, BK=32, 256 threads (8 warps, 4x2), warp tile 32x64.
// SMEM: 3 stages x (A 16K + B 16K) = 96KB. 2 CTAs/SM.
// EPI: 0 = bias, 1 = bias+GELU(exact), 2 = bias+residual
// ---------------------------------------------------------------------------
template<int EPI>
__global__ void __launch_bounds__(256, 2)
tgemm_kernel(const float* __restrict__ A,
             const float* __restrict__ W,
             const float* __restrict__ bias,
             const float* __restrict__ res,
             float* __restrict__ C,
             int M, int N, int K)
{
    extern __shared__ char smem[];
    const uint32_t sb = smem_u32(smem);
    const int tid   = threadIdx.x;
    const int wid   = tid >> 5;
    const int lane  = tid & 31;
    const int warpM = wid & 3;          // 0..3  -> 32-row slice
    const int warpN = wid >> 2;         // 0..1  -> 64-col slice
    const int m0 = blockIdx.y * 128;
    const int n0 = blockIdx.x * 128;

    // ldmatrix lane offsets (within a 128x32f tile, swizzled), ks=0
    uint32_t aOff[2], bOff[4];
    {
        const int r8 = (lane & 7) + ((lane >> 3) & 1) * 8;
        #pragma unroll
        for (int mf = 0; mf < 2; mf++) {
            const int row = warpM * 32 + mf * 16 + r8;
            aOff[mf] = sw128((uint32_t)(row * 128 + (lane >> 4) * 16));
        }
        const int rB = (lane & 7) + ((lane >> 4) & 1) * 8;
        #pragma unroll
        for (int p = 0; p < 4; p++) {
            const int row = warpN * 64 + p * 16 + rB;
            bOff[p] = sw128((uint32_t)(row * 128 + ((lane >> 3) & 1) * 16));
        }
    }

    float acc[2][8][4];
    #pragma unroll
    for (int i = 0; i < 2; i++)
        #pragma unroll
        for (int j = 0; j < 8; j++)
            #pragma unroll
            for (int q = 0; q < 4; q++) acc[i][j][q] = 0.f;

    const int nIter = K >> 5;
    const int lrow  = tid >> 3;          // 0..31, +g*32 -> rows 0..127
    const int lch   = tid & 7;           // 16B chunk within 128B row
    const uint32_t stOff = sw128((uint32_t)(lrow * 128 + lch * 16));
    const float* apt = A + (size_t)(m0 + lrow) * K + lch * 4;
    const float* bpt = W + (size_t)(n0 + lrow) * K + lch * 4;

    // prologue: stages 0,1 -> slots 0,1
    #pragma unroll
    for (int s = 0; s < 2; s++) {
        const int k0 = s << 5;
        const uint32_t dstA = sb + (uint32_t)s * 32768u + stOff;
        #pragma unroll
        for (int g = 0; g < 4; g++)
            CP_ASYNC16(dstA + g * 4096, apt + (size_t)g * 32 * K + k0);
        #pragma unroll
        for (int g = 0; g < 4; g++)
            CP_ASYNC16(dstA + 16384 + g * 4096, bpt + (size_t)g * 32 * K + k0);
        CP_COMMIT();
    }

    int slotNext = 2;   // slot for stage it+2
    for (int it = 0; it < nIter; ++it) {
        CP_WAIT1();            // stage it resident
        __syncthreads();       // all warps done with slot (it-1)%3

        // issue stage it+2 into slot (it+2)%3 (freed at it-1); empty group at tail
        if (it + 2 < nIter) {
            const int k0 = (it + 2) << 5;
            const uint32_t dstA = sb + (uint32_t)slotNext * 32768u + stOff;
            #pragma unroll
            for (int g = 0; g < 4; g++)
                CP_ASYNC16(dstA + g * 4096, apt + (size_t)g * 32 * K + k0);
            #pragma unroll
            for (int g = 0; g < 4; g++)
                CP_ASYNC16(dstA + 16384 + g * 4096, bpt + (size_t)g * 32 * K + k0);
        }
        CP_COMMIT();
        slotNext = (slotNext == 2) ? 0 : slotNext + 1;

        const uint32_t aB = sb + (uint32_t)(it % 3) * 32768u;
        const uint32_t bB = aB + 16384u;

        #pragma unroll
        for (int ks = 0; ks < 4; ks++) {
            const uint32_t kx = (uint32_t)(ks << 5);
            uint32_t af[2][4], bf[4][4];
            #pragma unroll
            for (int mf = 0; mf < 2; mf++) ldsm4(af[mf], aB + (aOff[mf] ^ kx));
            #pragma unroll
            for (int p = 0; p < 4; p++)   ldsm4(bf[p],  bB + (bOff[p]  ^ kx));
            #pragma unroll
            for (int mf = 0; mf < 2; mf++)
                #pragma unroll
                for (int nf = 0; nf < 8; nf++)
                    mma_tf32(acc[mf][nf], af[mf],
                             bf[nf >> 1][(nf & 1) * 2],
                             bf[nf >> 1][(nf & 1) * 2 + 1]);
        }
    }

    // epilogue
    #pragma unroll
    for (int mf = 0; mf < 2; mf++) {
        const int r0 = m0 + warpM * 32 + mf * 16 + (lane >> 2);
        #pragma unroll
        for (int nf = 0; nf < 8; nf++) {
            const int col = n0 + warpN * 64 + nf * 8 + (lane & 3) * 2;
            const float b0 = bias[col], b1 = bias[col + 1];
            #pragma unroll
            for (int h = 0; h < 2; h++) {
                const int r = r0 + h * 8;
                float v0 = acc[mf][nf][h * 2 + 0] + b0;
                float v1 = acc[mf][nf][h * 2 + 1] + b1;
                if (EPI == 1) {
                    v0 = 0.5f * v0 * (1.0f + erff(v0 * 0.70710678118654752f));
                    v1 = 0.5f * v1 * (1.0f + erff(v1 * 0.70710678118654752f));
                }
                if (EPI == 2) {
                    const float2 rr = *(const float2*)(res + (size_t)r * N + col);
                    v0 += rr.x; v1 += rr.y;
                }
                *(float2*)(C + (size_t)r * N + col) = make_float2(v0, v1);
            }
        }
    }
}

// ---------------------------------------------------------------------------
// Fused attention (flash-style, fp32) — unchanged
// ---------------------------------------------------------------------------
__global__ void __launch_bounds__(256)
attn_kernel(const float* __restrict__ qkv, float* __restrict__ out)
{
    __shared__ float Qt[64][64];
    __shared__ float KV[64][64];
    __shared__ float Ps[64][64];

    const int b  = blockIdx.z;
    const int h  = blockIdx.y;
    const int q0 = blockIdx.x * 64;

    const int tid = threadIdx.x;
    const int ty  = tid >> 4;
    const int tx  = tid & 15;

    const int lr = tid >> 2;
    const int lc = (tid & 3) * 16;

    const float scale = 0.03608439182435161f;   // 1/sqrt(768)
    const size_t rowstride = QKVD;

    {
        const float* qp = qkv + ((size_t)(b * SEQ + q0 + lr)) * rowstride + h * HDIM + lc;
        #pragma unroll
        for (int g = 0; g < 4; g++) {
            float4 v = *(const float4*)(qp + g * 4);
            Qt[lc + g * 4 + 0][lr] = v.x * scale;
            Qt[lc + g * 4 + 1][lr] = v.y * scale;
            Qt[lc + g * 4 + 2][lr] = v.z * scale;
            Qt[lc + g * 4 + 3][lr] = v.w * scale;
        }
    }
    __syncthreads();

    float m_i[4], l_i[4], o[4][4];
    #pragma unroll
    for (int i = 0; i < 4; i++) {
        m_i[i] = -1e30f; l_i[i] = 0.f;
        #pragma unroll
        for (int j = 0; j < 4; j++) o[i][j] = 0.f;
    }

    for (int t = 0; t < SEQ / 64; t++) {
        const size_t srow = (size_t)(b * SEQ + t * 64 + lr) * rowstride + h * HDIM + lc;
        float4 kr[4];
        {
            const float* kp = qkv + srow + DIM;
            #pragma unroll
            for (int g = 0; g < 4; g++) kr[g] = *(const float4*)(kp + g * 4);
        }
        __syncthreads();
        #pragma unroll
        for (int g = 0; g < 4; g++) {
            KV[lc + g * 4 + 0][lr] = kr[g].x;
            KV[lc + g * 4 + 1][lr] = kr[g].y;
            KV[lc + g * 4 + 2][lr] = kr[g].z;
            KV[lc + g * 4 + 3][lr] = kr[g].w;
        }
        __syncthreads();

        float s[4][4];
        #pragma unroll
        for (int i = 0; i < 4; i++)
            #pragma unroll
            for (int j = 0; j < 4; j++) s[i][j] = 0.f;
        #pragma unroll 8
        for (int d = 0; d < 64; d++) {
            float4 qa = *(const float4*)&Qt[d][ty * 4];
            float4 kb = *(const float4*)&KV[d][tx * 4];
            float a[4] = {qa.x, qa.y, qa.z, qa.w};
            float k4[4] = {kb.x, kb.y, kb.z, kb.w};
            #pragma unroll
            for (int i = 0; i < 4; i++)
                #pragma unroll
                for (int j = 0; j < 4; j++)
                    s[i][j] = fmaf(a[i], k4[j], s[i][j]);
        }

        float p[4][4];
        #pragma unroll
        for (int i = 0; i < 4; i++) {
            float rm = fmaxf(fmaxf(s[i][0], s[i][1]), fmaxf(s[i][2], s[i][3]));
            #pragma unroll
            for (int mk = 8; mk; mk >>= 1)
                rm = fmaxf(rm, __shfl_xor_sync(0xffffffffu, rm, mk));
            const float mn    = fmaxf(m_i[i], rm);
            const float alpha = __expf(m_i[i] - mn);
            float sum = 0.f;
            #pragma unroll
            for (int j = 0; j < 4; j++) { p[i][j] = __expf(s[i][j] - mn); sum += p[i][j]; }
            #pragma unroll
            for (int mk = 8; mk; mk >>= 1)
                sum += __shfl_xor_sync(0xffffffffu, sum, mk);
            l_i[i] = l_i[i] * alpha + sum;
            m_i[i] = mn;
            #pragma unroll
            for (int j = 0; j < 4; j++) o[i][j] *= alpha;
        }

        float4 vr[4];
        {
            const float* vp = qkv + srow + 2 * DIM;
            #pragma unroll
            for (int g = 0; g < 4; g++) vr[g] = *(const float4*)(vp + g * 4);
        }
        __syncthreads();
        #pragma unroll
        for (int g = 0; g < 4; g++)
            *(float4*)&KV[lr][lc + g * 4] = vr[g];
        #pragma unroll
        for (int i = 0; i < 4; i++)
            *(float4*)&Ps[ty * 4 + i][tx * 4] = make_float4(p[i][0], p[i][1], p[i][2], p[i][3]);
        __syncthreads();

        #pragma unroll 8
        for (int c = 0; c < 64; c++) {
            float4 vv = *(const float4*)&KV[c][tx * 4];
            float v4[4] = {vv.x, vv.y, vv.z, vv.w};
            #pragma unroll
            for (int i = 0; i < 4; i++) {
                float pv = Ps[ty * 4 + i][c];
                #pragma unroll
                for (int j = 0; j < 4; j++)
                    o[i][j] = fmaf(pv, v4[j], o[i][j]);
            }
        }
    }

    #pragma unroll
    for (int i = 0; i < 4; i++) {
        const float inv = 1.0f / l_i[i];
        float* op = out + (size_t)(b * SEQ + q0 + ty * 4 + i) * DIM + h * HDIM + tx * 4;
        *(float4*)op = make_float4(o[i][0] * inv, o[i][1] * inv, o[i][2] * inv, o[i][3] * inv);
    }
}

// ---------------------------------------------------------------------------
// Host entry
// ---------------------------------------------------------------------------
extern "C" void kernel_launch(void* const* d_in, const int* in_sizes, int n_in,
                              void* d_out, int out_size)
{
    const float* x     = (const float*)d_in[0];
    const float* ln_g  = (const float*)d_in[1];
    const float* ln_b  = (const float*)d_in[2];
    const float* w_qkv = (const float*)d_in[3];
    const float* b_qkv = (const float*)d_in[4];
    const float* w_out = (const float*)d_in[5];
    const float* b_out = (const float*)d_in[6];
    const float* w_fc1 = (const float*)d_in[7];
    const float* b_fc1 = (const float*)d_in[8];
    const float* w_fc2 = (const float*)d_in[9];
    const float* b_fc2 = (const float*)d_in[10];
    float* out = (float*)d_out;

    float *p_ln, *p_qkv, *p_att, *p_x1, *p_h;
    cudaGetSymbolAddress((void**)&p_ln,  g_ln);
    cudaGetSymbolAddress((void**)&p_qkv, g_qkv);
    cudaGetSymbolAddress((void**)&p_att, g_att);
    cudaGetSymbolAddress((void**)&p_x1,  g_x1);
    cudaGetSymbolAddress((void**)&p_h,   g_h);

    const int SMEM_BYTES = 98304;   // 3 stages x 32KB
    cudaFuncSetAttribute(tgemm_kernel<0>,
        cudaFuncAttributeMaxDynamicSharedMemorySize, SMEM_BYTES);
    cudaFuncSetAttribute(tgemm_kernel<1>,
        cudaFuncAttributeMaxDynamicSharedMemorySize, SMEM_BYTES);
    cudaFuncSetAttribute(tgemm_kernel<2>,
        cudaFuncAttributeMaxDynamicSharedMemorySize, SMEM_BYTES);

    // 1) ln1 = LN(x)
    ln_kernel<<<ROWS, 256>>>(x, ln_g, ln_b, p_ln);

    // 2) qkv = ln1 @ w_qkv^T + b_qkv
    tgemm_kernel<0><<<dim3(QKVD / 128, ROWS / 128), 256, SMEM_BYTES>>>(
        p_ln, w_qkv, b_qkv, nullptr, p_qkv, ROWS, QKVD, DIM);

    // 3) fused attention
    attn_kernel<<<dim3(SEQ / 64, HEADS, BATCH), 256>>>(p_qkv, p_att);

    // 4) x1 = x + att @ w_out^T + b_out
    tgemm_kernel<2><<<dim3(DIM / 128, ROWS / 128), 256, SMEM_BYTES>>>(
        p_att, w_out, b_out, x, p_x1, ROWS, DIM, DIM);

    // 5) ln2 = LN(x1)
    ln_kernel<<<ROWS, 256>>>(p_x1, ln_g, ln_b, p_ln);

    // 6) h = gelu(ln2 @ w_fc1^T + b_fc1)
    tgemm_kernel<1><<<dim3(HID / 128, ROWS / 128), 256, SMEM_BYTES>>>(
        p_ln, w_fc1, b_fc1, nullptr, p_h, ROWS, HID, DIM);

    // 7) out = x1 + h @ w_fc2^T + b_fc2
    tgemm_kernel<2><<<dim3(DIM / 128, ROWS / 128), 256, SMEM_BYTES>>>(
        p_h, w_fc2, b_fc2, p_x1, out, ROWS, DIM, HID);
}

// round 5
// speedup vs baseline: 4.0047x; 1.5922x over previous
#include <cuda_runtime.h>
#include <cuda_bf16.h>
#include <cstdint>
#include <math.h>

// ---------------------------------------------------------------------------
// Problem constants
// ---------------------------------------------------------------------------
#define BATCH 16
#define SEQ   1024
#define DIM   768
#define HEADS 12
#define HDIM  64
#define HID   3072
#define ROWS  (BATCH*SEQ)     // 16384
#define QKVD  (3*DIM)         // 2304

// ---------------------------------------------------------------------------
// Scratch (device globals — no allocation allowed)
// ---------------------------------------------------------------------------
__device__ float g_ln  [(size_t)ROWS * DIM];
__device__ float g_qkv [(size_t)ROWS * QKVD];
__device__ float g_att [(size_t)ROWS * DIM];
__device__ float g_x1  [(size_t)ROWS * DIM];
__device__ float g_h   [(size_t)ROWS * HID];

// ---------------------------------------------------------------------------
// Helpers
// ---------------------------------------------------------------------------
__device__ __forceinline__ uint32_t smem_u32(const void* p) {
    uint32_t a;
    asm("{ .reg .u64 t; cvta.to.shared.u64 t, %1; cvt.u32.u64 %0, t; }" : "=r"(a) : "l"(p));
    return a;
}
__device__ __forceinline__ void ldsm4(uint32_t* r, uint32_t addr) {
    asm volatile("ldmatrix.sync.aligned.m8n8.x4.shared.b16 {%0,%1,%2,%3}, [%4];"
        : "=r"(r[0]), "=r"(r[1]), "=r"(r[2]), "=r"(r[3]) : "r"(addr));
}
__device__ __forceinline__ void mma_tf32(float* c, const uint32_t* a,
                                         uint32_t b0, uint32_t b1) {
    asm volatile(
        "mma.sync.aligned.m16n8k8.row.col.f32.tf32.tf32.f32 "
        "{%0,%1,%2,%3}, {%4,%5,%6,%7}, {%8,%9}, {%0,%1,%2,%3};"
        : "+f"(c[0]), "+f"(c[1]), "+f"(c[2]), "+f"(c[3])
        : "r"(a[0]), "r"(a[1]), "r"(a[2]), "r"(a[3]), "r"(b0), "r"(b1));
}
__device__ __forceinline__ uint32_t sw128(uint32_t off) {
    return off ^ ((off >> 3) & 0x70);
}
#define CP_ASYNC16(dst, src) \
    asm volatile("cp.async.cg.shared.global [%0], [%1], 16;" \
                 :: "r"(dst), "l"(src) : "memory")
#define CP_COMMIT() asm volatile("cp.async.commit_group;" ::: "memory")
#define CP_WAIT1()  asm volatile("cp.async.wait_group 1;"  ::: "memory")

// ---------------------------------------------------------------------------
// LayerNorm: one block per row (D=768), 256 threads
// ---------------------------------------------------------------------------
__global__ void ln_kernel(const float* __restrict__ x,
                          const float* __restrict__ gg,
                          const float* __restrict__ bb,
                          float* __restrict__ y)
{
    const int row = blockIdx.x;
    const int tid = threadIdx.x;
    const float* xr = x + (size_t)row * DIM;

    float v0 = xr[tid], v1 = xr[tid + 256], v2 = xr[tid + 512];
    float s  = v0 + v1 + v2;
    float q  = v0*v0 + v1*v1 + v2*v2;

    #pragma unroll
    for (int m = 16; m; m >>= 1) {
        s += __shfl_xor_sync(0xffffffffu, s, m);
        q += __shfl_xor_sync(0xffffffffu, q, m);
    }
    __shared__ float sh[16];
    const int warp = tid >> 5, lane = tid & 31;
    if (!lane) { sh[warp] = s; sh[warp + 8] = q; }
    __syncthreads();
    if (tid == 0) {
        float ts = 0.f, tq = 0.f;
        #pragma unroll
        for (int w = 0; w < 8; w++) { ts += sh[w]; tq += sh[w + 8]; }
        sh[0] = ts * (1.0f / DIM);
        sh[8] = tq * (1.0f / DIM);
    }
    __syncthreads();
    const float mean = sh[0];
    const float var  = sh[8] - mean * mean;
    const float rstd = rsqrtf(var + 1e-5f);

    float* yr = y + (size_t)row * DIM;
    yr[tid      ] = (v0 - mean) * rstd * gg[tid      ] + bb[tid      ];
    yr[tid + 256] = (v1 - mean) * rstd * gg[tid + 256] + bb[tid + 256];
    yr[tid + 512] = (v2 - mean) * rstd * gg[tid + 512] + bb[tid + 512];
}

// ---------------------------------------------------------------------------
// tf32 mma.sync GEMM, cp.async 3-stage pipeline (unchanged from R4).
// ---------------------------------------------------------------------------
template<int EPI>
__global__ void __launch_bounds__(256, 2)
tgemm_kernel(const float* __restrict__ A,
             const float* __restrict__ W,
             const float* __restrict__ bias,
             const float* __restrict__ res,
             float* __restrict__ C,
             int M, int N, int K)
{
    extern __shared__ char smem[];
    const uint32_t sb = smem_u32(smem);
    const int tid   = threadIdx.x;
    const int wid   = tid >> 5;
    const int lane  = tid & 31;
    const int warpM = wid & 3;
    const int warpN = wid >> 2;
    const int m0 = blockIdx.y * 128;
    const int n0 = blockIdx.x * 128;

    uint32_t aOff[2], bOff[4];
    {
        const int r8 = (lane & 7) + ((lane >> 3) & 1) * 8;
        #pragma unroll
        for (int mf = 0; mf < 2; mf++) {
            const int row = warpM * 32 + mf * 16 + r8;
            aOff[mf] = sw128((uint32_t)(row * 128 + (lane >> 4) * 16));
        }
        const int rB = (lane & 7) + ((lane >> 4) & 1) * 8;
        #pragma unroll
        for (int p = 0; p < 4; p++) {
            const int row = warpN * 64 + p * 16 + rB;
            bOff[p] = sw128((uint32_t)(row * 128 + ((lane >> 3) & 1) * 16));
        }
    }

    float acc[2][8][4];
    #pragma unroll
    for (int i = 0; i < 2; i++)
        #pragma unroll
        for (int j = 0; j < 8; j++)
            #pragma unroll
            for (int q = 0; q < 4; q++) acc[i][j][q] = 0.f;

    const int nIter = K >> 5;
    const int lrow  = tid >> 3;
    const int lch   = tid & 7;
    const uint32_t stOff = sw128((uint32_t)(lrow * 128 + lch * 16));
    const float* apt = A + (size_t)(m0 + lrow) * K + lch * 4;
    const float* bpt = W + (size_t)(n0 + lrow) * K + lch * 4;

    #pragma unroll
    for (int s = 0; s < 2; s++) {
        const int k0 = s << 5;
        const uint32_t dstA = sb + (uint32_t)s * 32768u + stOff;
        #pragma unroll
        for (int g = 0; g < 4; g++)
            CP_ASYNC16(dstA + g * 4096, apt + (size_t)g * 32 * K + k0);
        #pragma unroll
        for (int g = 0; g < 4; g++)
            CP_ASYNC16(dstA + 16384 + g * 4096, bpt + (size_t)g * 32 * K + k0);
        CP_COMMIT();
    }

    int slotNext = 2;
    for (int it = 0; it < nIter; ++it) {
        CP_WAIT1();
        __syncthreads();

        if (it + 2 < nIter) {
            const int k0 = (it + 2) << 5;
            const uint32_t dstA = sb + (uint32_t)slotNext * 32768u + stOff;
            #pragma unroll
            for (int g = 0; g < 4; g++)
                CP_ASYNC16(dstA + g * 4096, apt + (size_t)g * 32 * K + k0);
            #pragma unroll
            for (int g = 0; g < 4; g++)
                CP_ASYNC16(dstA + 16384 + g * 4096, bpt + (size_t)g * 32 * K + k0);
        }
        CP_COMMIT();
        slotNext = (slotNext == 2) ? 0 : slotNext + 1;

        const uint32_t aB = sb + (uint32_t)(it % 3) * 32768u;
        const uint32_t bB = aB + 16384u;

        #pragma unroll
        for (int ks = 0; ks < 4; ks++) {
            const uint32_t kx = (uint32_t)(ks << 5);
            uint32_t af[2][4], bf[4][4];
            #pragma unroll
            for (int mf = 0; mf < 2; mf++) ldsm4(af[mf], aB + (aOff[mf] ^ kx));
            #pragma unroll
            for (int p = 0; p < 4; p++)   ldsm4(bf[p],  bB + (bOff[p]  ^ kx));
            #pragma unroll
            for (int mf = 0; mf < 2; mf++)
                #pragma unroll
                for (int nf = 0; nf < 8; nf++)
                    mma_tf32(acc[mf][nf], af[mf],
                             bf[nf >> 1][(nf & 1) * 2],
                             bf[nf >> 1][(nf & 1) * 2 + 1]);
        }
    }

    #pragma unroll
    for (int mf = 0; mf < 2; mf++) {
        const int r0 = m0 + warpM * 32 + mf * 16 + (lane >> 2);
        #pragma unroll
        for (int nf = 0; nf < 8; nf++) {
            const int col = n0 + warpN * 64 + nf * 8 + (lane & 3) * 2;
            const float b0 = bias[col], b1 = bias[col + 1];
            #pragma unroll
            for (int h = 0; h < 2; h++) {
                const int r = r0 + h * 8;
                float v0 = acc[mf][nf][h * 2 + 0] + b0;
                float v1 = acc[mf][nf][h * 2 + 1] + b1;
                if (EPI == 1) {
                    v0 = 0.5f * v0 * (1.0f + erff(v0 * 0.70710678118654752f));
                    v1 = 0.5f * v1 * (1.0f + erff(v1 * 0.70710678118654752f));
                }
                if (EPI == 2) {
                    const float2 rr = *(const float2*)(res + (size_t)r * N + col);
                    v0 += rr.x; v1 += rr.y;
                }
                *(float2*)(C + (size_t)r * N + col) = make_float2(v0, v1);
            }
        }
    }
}

// ---------------------------------------------------------------------------
// Tensor-core flash attention (tf32 mma).
// Block: 128 q-rows x (head, batch). 8 warps, each owns 16 q-rows.
// KV tiles of 64. S = QK^T via ldsm A(Q)/B(K); softmax in regs;
// P -> warp-private smem -> ldsm A frags; V B-frags via canonical lds.
// SMEM: Q 2x16K @0 | K 2x8K @32768 | V 2x8K @49152 | P 2x16K @65536 = 96KB
// ---------------------------------------------------------------------------
__global__ void __launch_bounds__(256, 2)
attn_kernel(const float* __restrict__ qkv, float* __restrict__ out)
{
    extern __shared__ char smem[];
    const uint32_t sb = smem_u32(smem);
    const uint32_t Q0 = 0u, K0 = 32768u, V0 = 49152u, P0 = 65536u;

    const int b  = blockIdx.z;
    const int h  = blockIdx.y;
    const int q0 = blockIdx.x * 128;
    const int tid = threadIdx.x, wid = tid >> 5, lane = tid & 31;

    const float scale = 0.03608439182435161f;   // 1/sqrt(768)

    // ---- load Q tile 128x64 (scaled) into 2 swizzled 128x32f tiles ----
    #pragma unroll
    for (int g = 0; g < 8; g++) {
        const int idx = tid + g * 256;          // 0..2047
        const int row = idx >> 4, ch = idx & 15;
        const float* qp = qkv + (size_t)(b * SEQ + q0 + row) * QKVD + h * HDIM + ch * 4;
        float4 v = *(const float4*)qp;
        v.x *= scale; v.y *= scale; v.z *= scale; v.w *= scale;
        const uint32_t off = sw128((uint32_t)(row * 128 + (ch & 7) * 16));
        *(float4*)(smem + Q0 + (uint32_t)(ch >> 3) * 16384u + off) = v;
    }

    // ---- fragment offsets ----
    uint32_t aOffQ, bOffK[4];
    {
        const int r8 = (lane & 7) + ((lane >> 3) & 1) * 8;
        aOffQ = sw128((uint32_t)((wid * 16 + r8) * 128 + (lane >> 4) * 16));
        const int rB = (lane & 7) + ((lane >> 4) & 1) * 8;
        #pragma unroll
        for (int p = 0; p < 4; p++)
            bOffK[p] = sw128((uint32_t)((p * 16 + rB) * 128 + ((lane >> 3) & 1) * 16));
    }
    const uint32_t aOffP = aOffQ;   // same row/chunk formula, 128B rows

    // V lds constants (canonical B frag: k=lane&3 (+4), n=lane>>2)
    const int vr    = lane & 3;
    const uint32_t xr0 = ((uint32_t)vr) << 4;          // swizzle XOR for row vr
    const uint32_t xr4 = ((uint32_t)(vr + 4)) << 4;    // for row vr+4
    const uint32_t vc4 = ((uint32_t)(lane >> 2)) << 2; // n within 8-col group (bytes)

    float accO[8][4];
    #pragma unroll
    for (int j = 0; j < 8; j++)
        #pragma unroll
        for (int q = 0; q < 4; q++) accO[j][q] = 0.f;
    float m_i[2] = {-1e30f, -1e30f}, l_i[2] = {0.f, 0.f};

    for (int t = 0; t < SEQ / 64; t++) {
        // ---- load K, V tiles (64x64 each) ----
        #pragma unroll
        for (int g = 0; g < 4; g++) {
            const int idx = tid + g * 256;      // 0..1023
            const int row = idx >> 4, ch = idx & 15;
            const float* kp = qkv + (size_t)(b * SEQ + t * 64 + row) * QKVD
                              + DIM + h * HDIM + ch * 4;
            float4 kv4 = *(const float4*)kp;
            float4 vv4 = *(const float4*)(kp + DIM);
            const uint32_t off = sw128((uint32_t)(row * 128 + (ch & 7) * 16));
            *(float4*)(smem + K0 + (uint32_t)(ch >> 3) * 8192u + off) = kv4;
            *(float4*)(smem + V0 + (uint32_t)(ch >> 3) * 8192u + off) = vv4;
        }
        __syncthreads();

        // ---- S = Q K^T : warp computes 16x64 ----
        float accS[8][4];
        #pragma unroll
        for (int j = 0; j < 8; j++)
            #pragma unroll
            for (int q = 0; q < 4; q++) accS[j][q] = 0.f;

        #pragma unroll
        for (int kstep = 0; kstep < 8; kstep++) {
            const uint32_t tileo = (uint32_t)(kstep >> 2);
            const uint32_t kx    = (uint32_t)((kstep & 3) << 5);
            uint32_t aq[4], bk[4][4];
            ldsm4(aq, sb + Q0 + tileo * 16384u + (aOffQ ^ kx));
            #pragma unroll
            for (int p = 0; p < 4; p++)
                ldsm4(bk[p], sb + K0 + tileo * 8192u + (bOffK[p] ^ kx));
            #pragma unroll
            for (int nf = 0; nf < 8; nf++)
                mma_tf32(accS[nf], aq,
                         bk[nf >> 1][(nf & 1) * 2],
                         bk[nf >> 1][(nf & 1) * 2 + 1]);
        }

        // ---- online softmax (rows: r=lane>>2 for c0/c1, r+8 for c2/c3) ----
        float mx0 = -1e30f, mx1 = -1e30f;
        #pragma unroll
        for (int nf = 0; nf < 8; nf++) {
            mx0 = fmaxf(mx0, fmaxf(accS[nf][0], accS[nf][1]));
            mx1 = fmaxf(mx1, fmaxf(accS[nf][2], accS[nf][3]));
        }
        mx0 = fmaxf(mx0, __shfl_xor_sync(0xffffffffu, mx0, 1));
        mx0 = fmaxf(mx0, __shfl_xor_sync(0xffffffffu, mx0, 2));
        mx1 = fmaxf(mx1, __shfl_xor_sync(0xffffffffu, mx1, 1));
        mx1 = fmaxf(mx1, __shfl_xor_sync(0xffffffffu, mx1, 2));

        const float mn0 = fmaxf(m_i[0], mx0), mn1 = fmaxf(m_i[1], mx1);
        const float al0 = __expf(m_i[0] - mn0), al1 = __expf(m_i[1] - mn1);
        float s0 = 0.f, s1 = 0.f;
        #pragma unroll
        for (int nf = 0; nf < 8; nf++) {
            accS[nf][0] = __expf(accS[nf][0] - mn0); s0 += accS[nf][0];
            accS[nf][1] = __expf(accS[nf][1] - mn0); s0 += accS[nf][1];
            accS[nf][2] = __expf(accS[nf][2] - mn1); s1 += accS[nf][2];
            accS[nf][3] = __expf(accS[nf][3] - mn1); s1 += accS[nf][3];
        }
        s0 += __shfl_xor_sync(0xffffffffu, s0, 1);
        s0 += __shfl_xor_sync(0xffffffffu, s0, 2);
        s1 += __shfl_xor_sync(0xffffffffu, s1, 1);
        s1 += __shfl_xor_sync(0xffffffffu, s1, 2);
        l_i[0] = l_i[0] * al0 + s0;  m_i[0] = mn0;
        l_i[1] = l_i[1] * al1 + s1;  m_i[1] = mn1;
        #pragma unroll
        for (int nf = 0; nf < 8; nf++) {
            accO[nf][0] *= al0; accO[nf][1] *= al0;
            accO[nf][2] *= al1; accO[nf][3] *= al1;
        }

        // ---- store P (warp-private rows) ----
        {
            const int r0 = wid * 16 + (lane >> 2);
            const uint32_t xrp = ((uint32_t)(r0 & 7)) << 4;
            #pragma unroll
            for (int nf = 0; nf < 8; nf++) {
                const uint32_t c8 = (uint32_t)((nf & 3) * 32 + (lane & 3) * 8);
                char* base = smem + P0 + (uint32_t)(nf >> 2) * 16384u;
                *(float2*)(base + (uint32_t)(r0 * 128) + (c8 ^ xrp)) =
                    make_float2(accS[nf][0], accS[nf][1]);
                *(float2*)(base + (uint32_t)((r0 + 8) * 128) + (c8 ^ xrp)) =
                    make_float2(accS[nf][2], accS[nf][3]);
            }
        }
        __syncwarp();

        // ---- O += P V ----
        #pragma unroll
        for (int kstep = 0; kstep < 8; kstep++) {
            uint32_t ap[4];
            ldsm4(ap, sb + P0 + (uint32_t)(kstep >> 2) * 16384u
                      + (aOffP ^ ((uint32_t)(kstep & 3) << 5)));
            const uint32_t ro  = (uint32_t)((kstep * 8 + vr) * 128);
            #pragma unroll
            for (int nf = 0; nf < 8; nf++) {
                const uint32_t cc = (uint32_t)((nf & 3) * 32) + vc4;
                const char* vb = smem + V0 + (uint32_t)(nf >> 2) * 8192u;
                const uint32_t b0 = *(const uint32_t*)(vb + ro + (cc ^ xr0));
                const uint32_t b1 = *(const uint32_t*)(vb + ro + 512u + (cc ^ xr4));
                mma_tf32(accO[nf], ap, b0, b1);
            }
        }
        __syncthreads();
    }

    // ---- normalize + store ----
    {
        const int r0 = wid * 16 + (lane >> 2);
        #pragma unroll
        for (int half = 0; half < 2; half++) {
            const int r = r0 + half * 8;
            const float inv = 1.0f / l_i[half];
            float* op = out + (size_t)(b * SEQ + q0 + r) * DIM + h * HDIM;
            #pragma unroll
            for (int nf = 0; nf < 8; nf++) {
                *(float2*)(op + nf * 8 + (lane & 3) * 2) =
                    make_float2(accO[nf][half * 2] * inv,
                                accO[nf][half * 2 + 1] * inv);
            }
        }
    }
}

// ---------------------------------------------------------------------------
// Host entry
// ---------------------------------------------------------------------------
extern "C" void kernel_launch(void* const* d_in, const int* in_sizes, int n_in,
                              void* d_out, int out_size)
{
    const float* x     = (const float*)d_in[0];
    const float* ln_g  = (const float*)d_in[1];
    const float* ln_b  = (const float*)d_in[2];
    const float* w_qkv = (const float*)d_in[3];
    const float* b_qkv = (const float*)d_in[4];
    const float* w_out = (const float*)d_in[5];
    const float* b_out = (const float*)d_in[6];
    const float* w_fc1 = (const float*)d_in[7];
    const float* b_fc1 = (const float*)d_in[8];
    const float* w_fc2 = (const float*)d_in[9];
    const float* b_fc2 = (const float*)d_in[10];
    float* out = (float*)d_out;

    float *p_ln, *p_qkv, *p_att, *p_x1, *p_h;
    cudaGetSymbolAddress((void**)&p_ln,  g_ln);
    cudaGetSymbolAddress((void**)&p_qkv, g_qkv);
    cudaGetSymbolAddress((void**)&p_att, g_att);
    cudaGetSymbolAddress((void**)&p_x1,  g_x1);
    cudaGetSymbolAddress((void**)&p_h,   g_h);

    const int SMEM_G = 98304;   // GEMM: 3 stages x 32KB
    const int SMEM_A = 98304;   // attn: Q32 + K16 + V16 + P32
    cudaFuncSetAttribute(tgemm_kernel<0>,
        cudaFuncAttributeMaxDynamicSharedMemorySize, SMEM_G);
    cudaFuncSetAttribute(tgemm_kernel<1>,
        cudaFuncAttributeMaxDynamicSharedMemorySize, SMEM_G);
    cudaFuncSetAttribute(tgemm_kernel<2>,
        cudaFuncAttributeMaxDynamicSharedMemorySize, SMEM_G);
    cudaFuncSetAttribute(attn_kernel,
        cudaFuncAttributeMaxDynamicSharedMemorySize, SMEM_A);

    // 1) ln1 = LN(x)
    ln_kernel<<<ROWS, 256>>>(x, ln_g, ln_b, p_ln);

    // 2) qkv = ln1 @ w_qkv^T + b_qkv
    tgemm_kernel<0><<<dim3(QKVD / 128, ROWS / 128), 256, SMEM_G>>>(
        p_ln, w_qkv, b_qkv, nullptr, p_qkv, ROWS, QKVD, DIM);

    // 3) fused attention (tensor cores)
    attn_kernel<<<dim3(SEQ / 128, HEADS, BATCH), 256, SMEM_A>>>(p_qkv, p_att);

    // 4) x1 = x + att @ w_out^T + b_out
    tgemm_kernel<2><<<dim3(DIM / 128, ROWS / 128), 256, SMEM_G>>>(
        p_att, w_out, b_out, x, p_x1, ROWS, DIM, DIM);

    // 5) ln2 = LN(x1)
    ln_kernel<<<ROWS, 256>>>(p_x1, ln_g, ln_b, p_ln);

    // 6) h = gelu(ln2 @ w_fc1^T + b_fc1)
    tgemm_kernel<1><<<dim3(HID / 128, ROWS / 128), 256, SMEM_G>>>(
        p_ln, w_fc1, b_fc1, nullptr, p_h, ROWS, HID, DIM);

    // 7) out = x1 + h @ w_fc2^T + b_fc2
    tgemm_kernel<2><<<dim3(DIM / 128, ROWS / 128), 256, SMEM_G>>>(
        p_h, w_fc2, b_fc2, p_x1, out, ROWS, DIM, HID);
}

// round 6
// speedup vs baseline: 7.1969x; 1.7971x over previous
#include <cuda_runtime.h>
#include <cuda_fp16.h>
#include <cstdint>
#include <math.h>

// ---------------------------------------------------------------------------
// Problem constants
// ---------------------------------------------------------------------------
#define BATCH 16
#define SEQ   1024
#define DIM   768
#define HEADS 12
#define HDIM  64
#define HID   3072
#define ROWS  (BATCH*SEQ)     // 16384
#define QKVD  (3*DIM)         // 2304

// ---------------------------------------------------------------------------
// Scratch (device globals — no allocation allowed)
// ---------------------------------------------------------------------------
__device__ __half g_lnh [(size_t)ROWS * DIM];
__device__ __half g_qkvh[(size_t)ROWS * QKVD];
__device__ __half g_atth[(size_t)ROWS * DIM];
__device__ __half g_hh  [(size_t)ROWS * HID];
__device__ float  g_x1  [(size_t)ROWS * DIM];
__device__ __half g_wqkvh[(size_t)QKVD * DIM];
__device__ __half g_wouth[(size_t)DIM * DIM];
__device__ __half g_wfc1h[(size_t)HID * DIM];
__device__ __half g_wfc2h[(size_t)DIM * HID];

// ---------------------------------------------------------------------------
// Helpers
// ---------------------------------------------------------------------------
__device__ __forceinline__ uint32_t smem_u32(const void* p) {
    uint32_t a;
    asm("{ .reg .u64 t; cvta.to.shared.u64 t, %1; cvt.u32.u64 %0, t; }" : "=r"(a) : "l"(p));
    return a;
}
__device__ __forceinline__ void ldsm4(uint32_t* r, uint32_t addr) {
    asm volatile("ldmatrix.sync.aligned.m8n8.x4.shared.b16 {%0,%1,%2,%3}, [%4];"
        : "=r"(r[0]), "=r"(r[1]), "=r"(r[2]), "=r"(r[3]) : "r"(addr));
}
__device__ __forceinline__ void ldsm4t(uint32_t* r, uint32_t addr) {
    asm volatile("ldmatrix.sync.aligned.m8n8.x4.trans.shared.b16 {%0,%1,%2,%3}, [%4];"
        : "=r"(r[0]), "=r"(r[1]), "=r"(r[2]), "=r"(r[3]) : "r"(addr));
}
__device__ __forceinline__ void mma_f16(float* c, const uint32_t* a,
                                        uint32_t b0, uint32_t b1) {
    asm volatile(
        "mma.sync.aligned.m16n8k16.row.col.f32.f16.f16.f32 "
        "{%0,%1,%2,%3}, {%4,%5,%6,%7}, {%8,%9}, {%0,%1,%2,%3};"
        : "+f"(c[0]), "+f"(c[1]), "+f"(c[2]), "+f"(c[3])
        : "r"(a[0]), "r"(a[1]), "r"(a[2]), "r"(a[3]), "r"(b0), "r"(b1));
}
__device__ __forceinline__ uint32_t sw128(uint32_t off) {
    return off ^ ((off >> 3) & 0x70);
}
#define CP_ASYNC16(dst, src) \
    asm volatile("cp.async.cg.shared.global [%0], [%1], 16;" \
                 :: "r"(dst), "l"(src) : "memory")
#define CP_COMMIT() asm volatile("cp.async.commit_group;" ::: "memory")
#define CP_WAIT1()  asm volatile("cp.async.wait_group 1;"  ::: "memory")

// ---------------------------------------------------------------------------
// fp32 -> fp16 conversion (weights), 4 elems/thread
// ---------------------------------------------------------------------------
__global__ void f2h_kernel(const float* __restrict__ s, __half* __restrict__ d, int n)
{
    const int i = (blockIdx.x * 256 + threadIdx.x) * 4;
    if (i < n) {
        float4 v = *(const float4*)(s + i);
        *(__half2*)(d + i)     = __floats2half2_rn(v.x, v.y);
        *(__half2*)(d + i + 2) = __floats2half2_rn(v.z, v.w);
    }
}

// ---------------------------------------------------------------------------
// LayerNorm: one block per row (D=768), 256 threads, fp32 in -> fp16 out
// ---------------------------------------------------------------------------
__global__ void ln_kernel(const float* __restrict__ x,
                          const float* __restrict__ gg,
                          const float* __restrict__ bb,
                          __half* __restrict__ y)
{
    const int row = blockIdx.x;
    const int tid = threadIdx.x;
    const float* xr = x + (size_t)row * DIM;

    float v0 = xr[tid], v1 = xr[tid + 256], v2 = xr[tid + 512];
    float s  = v0 + v1 + v2;
    float q  = v0*v0 + v1*v1 + v2*v2;

    #pragma unroll
    for (int m = 16; m; m >>= 1) {
        s += __shfl_xor_sync(0xffffffffu, s, m);
        q += __shfl_xor_sync(0xffffffffu, q, m);
    }
    __shared__ float sh[16];
    const int warp = tid >> 5, lane = tid & 31;
    if (!lane) { sh[warp] = s; sh[warp + 8] = q; }
    __syncthreads();
    if (tid == 0) {
        float ts = 0.f, tq = 0.f;
        #pragma unroll
        for (int w = 0; w < 8; w++) { ts += sh[w]; tq += sh[w + 8]; }
        sh[0] = ts * (1.0f / DIM);
        sh[8] = tq * (1.0f / DIM);
    }
    __syncthreads();
    const float mean = sh[0];
    const float var  = sh[8] - mean * mean;
    const float rstd = rsqrtf(var + 1e-5f);

    __half* yr = y + (size_t)row * DIM;
    yr[tid      ] = __float2half_rn((v0 - mean) * rstd * gg[tid      ] + bb[tid      ]);
    yr[tid + 256] = __float2half_rn((v1 - mean) * rstd * gg[tid + 256] + bb[tid + 256]);
    yr[tid + 512] = __float2half_rn((v2 - mean) * rstd * gg[tid + 512] + bb[tid + 512]);
}

// ---------------------------------------------------------------------------
// fp16 mma.sync GEMM, cp.async 3-stage pipeline.
// C[M,N] = A[M,K]h @ W[N,K]h^T + bias (+ epilogue), fp32 accumulate.
// Tile 128x128, BK=64 (4 k16 steps), 256 threads (8 warps 4x2), warp 32x64.
// SMEM: 3 stages x (A 16K + B 16K) = 96KB. 2 CTAs/SM.
// EPI: 0 = bias, 1 = bias+GELU(exact), 2 = bias+residual(fp32)
// HALF_OUT: output __half (true) or float (false)
// ---------------------------------------------------------------------------
template<int EPI, bool HALF_OUT>
__global__ void __launch_bounds__(256, 2)
tgemm_kernel(const __half* __restrict__ A,
             const __half* __restrict__ W,
             const float* __restrict__ bias,
             const float* __restrict__ res,
             void* __restrict__ Cv,
             int M, int N, int K)
{
    extern __shared__ char smem[];
    const uint32_t sb = smem_u32(smem);
    const int tid   = threadIdx.x;
    const int wid   = tid >> 5;
    const int lane  = tid & 31;
    const int warpM = wid & 3;
    const int warpN = wid >> 2;
    const int m0 = blockIdx.y * 128;
    const int n0 = blockIdx.x * 128;

    uint32_t aOff[2], bOff[4];
    {
        const int r8 = (lane & 7) + ((lane >> 3) & 1) * 8;
        #pragma unroll
        for (int mf = 0; mf < 2; mf++) {
            const int row = warpM * 32 + mf * 16 + r8;
            aOff[mf] = sw128((uint32_t)(row * 128 + (lane >> 4) * 16));
        }
        const int rB = (lane & 7) + ((lane >> 4) & 1) * 8;
        #pragma unroll
        for (int p = 0; p < 4; p++) {
            const int row = warpN * 64 + p * 16 + rB;
            bOff[p] = sw128((uint32_t)(row * 128 + ((lane >> 3) & 1) * 16));
        }
    }

    float acc[2][8][4];
    #pragma unroll
    for (int i = 0; i < 2; i++)
        #pragma unroll
        for (int j = 0; j < 8; j++)
            #pragma unroll
            for (int q = 0; q < 4; q++) acc[i][j][q] = 0.f;

    const int nIter = K >> 6;                 // BK = 64 halfs
    const int lrow  = tid >> 3;               // 0..31 (+g*32)
    const int lch   = tid & 7;                // 16B chunk in 128B row
    const uint32_t stOff = sw128((uint32_t)(lrow * 128 + lch * 16));
    const __half* apt = A + (size_t)(m0 + lrow) * K + lch * 8;
    const __half* bpt = W + (size_t)(n0 + lrow) * K + lch * 8;

    #pragma unroll
    for (int s = 0; s < 2; s++) {
        const int k0 = s << 6;
        const uint32_t dstA = sb + (uint32_t)s * 32768u + stOff;
        #pragma unroll
        for (int g = 0; g < 4; g++)
            CP_ASYNC16(dstA + g * 4096, apt + (size_t)g * 32 * K + k0);
        #pragma unroll
        for (int g = 0; g < 4; g++)
            CP_ASYNC16(dstA + 16384 + g * 4096, bpt + (size_t)g * 32 * K + k0);
        CP_COMMIT();
    }

    int slotNext = 2;
    for (int it = 0; it < nIter; ++it) {
        CP_WAIT1();
        __syncthreads();

        if (it + 2 < nIter) {
            const int k0 = (it + 2) << 6;
            const uint32_t dstA = sb + (uint32_t)slotNext * 32768u + stOff;
            #pragma unroll
            for (int g = 0; g < 4; g++)
                CP_ASYNC16(dstA + g * 4096, apt + (size_t)g * 32 * K + k0);
            #pragma unroll
            for (int g = 0; g < 4; g++)
                CP_ASYNC16(dstA + 16384 + g * 4096, bpt + (size_t)g * 32 * K + k0);
        }
        CP_COMMIT();
        slotNext = (slotNext == 2) ? 0 : slotNext + 1;

        const uint32_t aB = sb + (uint32_t)(it % 3) * 32768u;
        const uint32_t bB = aB + 16384u;

        #pragma unroll
        for (int ks = 0; ks < 4; ks++) {       // 4 x k16
            const uint32_t kx = (uint32_t)(ks << 5);   // 32B = 16 halfs
            uint32_t af[2][4], bf[4][4];
            #pragma unroll
            for (int mf = 0; mf < 2; mf++) ldsm4(af[mf], aB + (aOff[mf] ^ kx));
            #pragma unroll
            for (int p = 0; p < 4; p++)   ldsm4(bf[p],  bB + (bOff[p]  ^ kx));
            #pragma unroll
            for (int mf = 0; mf < 2; mf++)
                #pragma unroll
                for (int nf = 0; nf < 8; nf++)
                    mma_f16(acc[mf][nf], af[mf],
                            bf[nf >> 1][(nf & 1) * 2],
                            bf[nf >> 1][(nf & 1) * 2 + 1]);
        }
    }

    // epilogue
    #pragma unroll
    for (int mf = 0; mf < 2; mf++) {
        const int r0 = m0 + warpM * 32 + mf * 16 + (lane >> 2);
        #pragma unroll
        for (int nf = 0; nf < 8; nf++) {
            const int col = n0 + warpN * 64 + nf * 8 + (lane & 3) * 2;
            const float b0 = bias[col], b1 = bias[col + 1];
            #pragma unroll
            for (int h = 0; h < 2; h++) {
                const int r = r0 + h * 8;
                float v0 = acc[mf][nf][h * 2 + 0] + b0;
                float v1 = acc[mf][nf][h * 2 + 1] + b1;
                if (EPI == 1) {
                    v0 = 0.5f * v0 * (1.0f + erff(v0 * 0.70710678118654752f));
                    v1 = 0.5f * v1 * (1.0f + erff(v1 * 0.70710678118654752f));
                }
                if (EPI == 2) {
                    const float2 rr = *(const float2*)(res + (size_t)r * N + col);
                    v0 += rr.x; v1 += rr.y;
                }
                if (HALF_OUT) {
                    *(__half2*)((__half*)Cv + (size_t)r * N + col) =
                        __floats2half2_rn(v0, v1);
                } else {
                    *(float2*)((float*)Cv + (size_t)r * N + col) =
                        make_float2(v0, v1);
                }
            }
        }
    }
}

// ---------------------------------------------------------------------------
// fp16 tensor-core flash attention.
// Block: 128 q-rows x (head, batch). 8 warps x 16 q-rows. KV tiles of 64.
// SMEM: Q 16K @0 | K 8K @16384 | V 8K @24576 | P 16K @32768 = 48KB
// ---------------------------------------------------------------------------
__global__ void __launch_bounds__(256, 2)
attn_kernel(const __half* __restrict__ qkv, __half* __restrict__ out)
{
    extern __shared__ char smem[];
    const uint32_t sb = smem_u32(smem);
    const uint32_t Q0 = 0u, K0 = 16384u, V0 = 24576u, P0 = 32768u;

    const int b  = blockIdx.z;
    const int h  = blockIdx.y;
    const int q0 = blockIdx.x * 128;
    const int tid = threadIdx.x, wid = tid >> 5, lane = tid & 31;

    const float scale = 0.03608439182435161f;   // 1/sqrt(768)

    // ---- load Q tile 128x64 (raw halves, 128B rows, sw128) ----
    #pragma unroll
    for (int g = 0; g < 4; g++) {
        const int idx = tid + g * 256;          // 0..1023
        const int row = idx >> 3, ch = idx & 7;
        const __half* qp = qkv + (size_t)(b * SEQ + q0 + row) * QKVD + h * HDIM + ch * 8;
        *(uint4*)(smem + Q0 + sw128((uint32_t)(row * 128 + ch * 16))) =
            *(const uint4*)qp;
    }

    // ---- fragment offsets ----
    uint32_t aOffQ, bOffK[4], bOffV[4];
    {
        const int r8 = (lane & 7) + ((lane >> 3) & 1) * 8;
        aOffQ = sw128((uint32_t)((wid * 16 + r8) * 128 + (lane >> 4) * 16));
        const int rB = (lane & 7) + ((lane >> 4) & 1) * 8;
        #pragma unroll
        for (int p = 0; p < 4; p++)
            bOffK[p] = sw128((uint32_t)((p * 16 + rB) * 128 + ((lane >> 3) & 1) * 16));
        // V (trans): kv row within 16-step, d chunk per pair
        #pragma unroll
        for (int p = 0; p < 4; p++)
            bOffV[p] = sw128((uint32_t)(r8 * 128 + p * 32 + ((lane >> 4) & 1) * 16));
    }
    const uint32_t aOffP = aOffQ;

    float accO[8][4];
    #pragma unroll
    for (int j = 0; j < 8; j++)
        #pragma unroll
        for (int q = 0; q < 4; q++) accO[j][q] = 0.f;
    float m_i[2] = {-1e30f, -1e30f}, l_i[2] = {0.f, 0.f};

    // P store constants
    const int pr = wid * 16 + (lane >> 2);
    const uint32_t xrp = ((uint32_t)(pr & 7)) << 4;
    const uint32_t pcb = (uint32_t)((lane & 3) * 4);

    for (int t = 0; t < SEQ / 64; t++) {
        // ---- load K, V tiles (64x64 half each) ----
        #pragma unroll
        for (int g = 0; g < 2; g++) {
            const int idx = tid + g * 256;      // 0..511
            const int row = idx >> 3, ch = idx & 7;
            const __half* kp = qkv + (size_t)(b * SEQ + t * 64 + row) * QKVD
                               + DIM + h * HDIM + ch * 8;
            const uint32_t off = sw128((uint32_t)(row * 128 + ch * 16));
            *(uint4*)(smem + K0 + off) = *(const uint4*)kp;
            *(uint4*)(smem + V0 + off) = *(const uint4*)(kp + DIM);
        }
        __syncthreads();

        // ---- S = Q K^T : warp computes 16x64, fp32 accum ----
        float accS[8][4];
        #pragma unroll
        for (int j = 0; j < 8; j++)
            #pragma unroll
            for (int q = 0; q < 4; q++) accS[j][q] = 0.f;

        #pragma unroll
        for (int ds = 0; ds < 4; ds++) {        // d = 4 x k16
            const uint32_t kx = (uint32_t)(ds << 5);
            uint32_t aq[4], bk[4][4];
            ldsm4(aq, sb + Q0 + (aOffQ ^ kx));
            #pragma unroll
            for (int p = 0; p < 4; p++)
                ldsm4(bk[p], sb + K0 + (bOffK[p] ^ kx));
            #pragma unroll
            for (int nf = 0; nf < 8; nf++)
                mma_f16(accS[nf], aq,
                        bk[nf >> 1][(nf & 1) * 2],
                        bk[nf >> 1][(nf & 1) * 2 + 1]);
        }
        #pragma unroll
        for (int nf = 0; nf < 8; nf++)
            #pragma unroll
            for (int q = 0; q < 4; q++) accS[nf][q] *= scale;

        // ---- online softmax ----
        float mx0 = -1e30f, mx1 = -1e30f;
        #pragma unroll
        for (int nf = 0; nf < 8; nf++) {
            mx0 = fmaxf(mx0, fmaxf(accS[nf][0], accS[nf][1]));
            mx1 = fmaxf(mx1, fmaxf(accS[nf][2], accS[nf][3]));
        }
        mx0 = fmaxf(mx0, __shfl_xor_sync(0xffffffffu, mx0, 1));
        mx0 = fmaxf(mx0, __shfl_xor_sync(0xffffffffu, mx0, 2));
        mx1 = fmaxf(mx1, __shfl_xor_sync(0xffffffffu, mx1, 1));
        mx1 = fmaxf(mx1, __shfl_xor_sync(0xffffffffu, mx1, 2));

        const float mn0 = fmaxf(m_i[0], mx0), mn1 = fmaxf(m_i[1], mx1);
        const float al0 = __expf(m_i[0] - mn0), al1 = __expf(m_i[1] - mn1);
        float s0 = 0.f, s1 = 0.f;
        #pragma unroll
        for (int nf = 0; nf < 8; nf++) {
            accS[nf][0] = __expf(accS[nf][0] - mn0); s0 += accS[nf][0];
            accS[nf][1] = __expf(accS[nf][1] - mn0); s0 += accS[nf][1];
            accS[nf][2] = __expf(accS[nf][2] - mn1); s1 += accS[nf][2];
            accS[nf][3] = __expf(accS[nf][3] - mn1); s1 += accS[nf][3];
        }
        s0 += __shfl_xor_sync(0xffffffffu, s0, 1);
        s0 += __shfl_xor_sync(0xffffffffu, s0, 2);
        s1 += __shfl_xor_sync(0xffffffffu, s1, 1);
        s1 += __shfl_xor_sync(0xffffffffu, s1, 2);
        l_i[0] = l_i[0] * al0 + s0;  m_i[0] = mn0;
        l_i[1] = l_i[1] * al1 + s1;  m_i[1] = mn1;
        #pragma unroll
        for (int nf = 0; nf < 8; nf++) {
            accO[nf][0] *= al0; accO[nf][1] *= al0;
            accO[nf][2] *= al1; accO[nf][3] *= al1;
        }

        // ---- store P as half2 (warp-private rows) ----
        #pragma unroll
        for (int nf = 0; nf < 8; nf++) {
            const uint32_t cb = (uint32_t)(nf * 16) + pcb;
            *(__half2*)(smem + P0 + (uint32_t)(pr * 128) + (cb ^ xrp)) =
                __floats2half2_rn(accS[nf][0], accS[nf][1]);
            *(__half2*)(smem + P0 + (uint32_t)((pr + 8) * 128) + (cb ^ xrp)) =
                __floats2half2_rn(accS[nf][2], accS[nf][3]);
        }
        __syncwarp();

        // ---- O += P V ----
        #pragma unroll
        for (int ks = 0; ks < 4; ks++) {        // kv = 4 x k16
            uint32_t ap[4], bv[4][4];
            ldsm4(ap, sb + P0 + (aOffP ^ ((uint32_t)(ks << 5))));
            #pragma unroll
            for (int p = 0; p < 4; p++)
                ldsm4t(bv[p], sb + V0 + bOffV[p] + (uint32_t)(ks * 2048));
            #pragma unroll
            for (int nf = 0; nf < 8; nf++)
                mma_f16(accO[nf], ap,
                        bv[nf >> 1][(nf & 1) * 2],
                        bv[nf >> 1][(nf & 1) * 2 + 1]);
        }
        __syncthreads();
    }

    // ---- normalize + store (half) ----
    {
        const int r0 = wid * 16 + (lane >> 2);
        #pragma unroll
        for (int half = 0; half < 2; half++) {
            const int r = r0 + half * 8;
            const float inv = 1.0f / l_i[half];
            __half* op = out + (size_t)(b * SEQ + q0 + r) * DIM + h * HDIM;
            #pragma unroll
            for (int nf = 0; nf < 8; nf++)
                *(__half2*)(op + nf * 8 + (lane & 3) * 2) =
                    __floats2half2_rn(accO[nf][half * 2] * inv,
                                      accO[nf][half * 2 + 1] * inv);
        }
    }
}

// ---------------------------------------------------------------------------
// Host entry
// ---------------------------------------------------------------------------
extern "C" void kernel_launch(void* const* d_in, const int* in_sizes, int n_in,
                              void* d_out, int out_size)
{
    const float* x     = (const float*)d_in[0];
    const float* ln_g  = (const float*)d_in[1];
    const float* ln_b  = (const float*)d_in[2];
    const float* w_qkv = (const float*)d_in[3];
    const float* b_qkv = (const float*)d_in[4];
    const float* w_out = (const float*)d_in[5];
    const float* b_out = (const float*)d_in[6];
    const float* w_fc1 = (const float*)d_in[7];
    const float* b_fc1 = (const float*)d_in[8];
    const float* w_fc2 = (const float*)d_in[9];
    const float* b_fc2 = (const float*)d_in[10];
    float* out = (float*)d_out;

    __half *p_lnh, *p_qkvh, *p_atth, *p_hh;
    __half *p_wqkv, *p_wout, *p_wfc1, *p_wfc2;
    float  *p_x1;
    cudaGetSymbolAddress((void**)&p_lnh,  g_lnh);
    cudaGetSymbolAddress((void**)&p_qkvh, g_qkvh);
    cudaGetSymbolAddress((void**)&p_atth, g_atth);
    cudaGetSymbolAddress((void**)&p_hh,   g_hh);
    cudaGetSymbolAddress((void**)&p_x1,   g_x1);
    cudaGetSymbolAddress((void**)&p_wqkv, g_wqkvh);
    cudaGetSymbolAddress((void**)&p_wout, g_wouth);
    cudaGetSymbolAddress((void**)&p_wfc1, g_wfc1h);
    cudaGetSymbolAddress((void**)&p_wfc2, g_wfc2h);

    const int SMEM_G = 98304;   // GEMM: 3 stages x 32KB
    const int SMEM_A = 49152;   // attn: Q16 + K8 + V8 + P16
    cudaFuncSetAttribute(tgemm_kernel<0, true>,
        cudaFuncAttributeMaxDynamicSharedMemorySize, SMEM_G);
    cudaFuncSetAttribute(tgemm_kernel<1, true>,
        cudaFuncAttributeMaxDynamicSharedMemorySize, SMEM_G);
    cudaFuncSetAttribute(tgemm_kernel<2, false>,
        cudaFuncAttributeMaxDynamicSharedMemorySize, SMEM_G);
    cudaFuncSetAttribute(attn_kernel,
        cudaFuncAttributeMaxDynamicSharedMemorySize, SMEM_A);

    // 0) convert weights to fp16
    f2h_kernel<<<(QKVD * DIM / 4 + 255) / 256, 256>>>(w_qkv, p_wqkv, QKVD * DIM);
    f2h_kernel<<<(DIM * DIM  / 4 + 255) / 256, 256>>>(w_out, p_wout, DIM * DIM);
    f2h_kernel<<<(HID * DIM  / 4 + 255) / 256, 256>>>(w_fc1, p_wfc1, HID * DIM);
    f2h_kernel<<<(DIM * HID  / 4 + 255) / 256, 256>>>(w_fc2, p_wfc2, DIM * HID);

    // 1) ln1 = LN(x) -> half
    ln_kernel<<<ROWS, 256>>>(x, ln_g, ln_b, p_lnh);

    // 2) qkv = ln1 @ w_qkv^T + b_qkv -> half
    tgemm_kernel<0, true><<<dim3(QKVD / 128, ROWS / 128), 256, SMEM_G>>>(
        p_lnh, p_wqkv, b_qkv, nullptr, p_qkvh, ROWS, QKVD, DIM);

    // 3) fused attention -> half
    attn_kernel<<<dim3(SEQ / 128, HEADS, BATCH), 256, SMEM_A>>>(p_qkvh, p_atth);

    // 4) x1 = x + att @ w_out^T + b_out  (fp32)
    tgemm_kernel<2, false><<<dim3(DIM / 128, ROWS / 128), 256, SMEM_G>>>(
        p_atth, p_wout, b_out, x, p_x1, ROWS, DIM, DIM);

    // 5) ln2 = LN(x1) -> half
    ln_kernel<<<ROWS, 256>>>(p_x1, ln_g, ln_b, p_lnh);

    // 6) h = gelu(ln2 @ w_fc1^T + b_fc1) -> half
    tgemm_kernel<1, true><<<dim3(HID / 128, ROWS / 128), 256, SMEM_G>>>(
        p_lnh, p_wfc1, b_fc1, nullptr, p_hh, ROWS, HID, DIM);

    // 7) out = x1 + h @ w_fc2^T + b_fc2  (fp32)
    tgemm_kernel<2, false><<<dim3(DIM / 128, ROWS / 128), 256, SMEM_G>>>(
        p_hh, p_wfc2, b_fc2, p_x1, out, ROWS, DIM, HID);
}

// round 7
// speedup vs baseline: 7.5488x; 1.0489x over previous
#include <cuda_runtime.h>
#include <cuda_fp16.h>
#include <cstdint>
#include <math.h>

// ---------------------------------------------------------------------------
// Problem constants
// ---------------------------------------------------------------------------
#define BATCH 16
#define SEQ   1024
#define DIM   768
#define HEADS 12
#define HDIM  64
#define HID   3072
#define ROWS  (BATCH*SEQ)     // 16384
#define QKVD  (3*DIM)         // 2304

// ---------------------------------------------------------------------------
// Scratch (device globals — no allocation allowed)
// ---------------------------------------------------------------------------
__device__ __half g_lnh [(size_t)ROWS * DIM];
__device__ __half g_qkvh[(size_t)ROWS * QKVD];
__device__ __half g_atth[(size_t)ROWS * DIM];
__device__ __half g_hh  [(size_t)ROWS * HID];
__device__ float  g_x1  [(size_t)ROWS * DIM];
__device__ __half g_wqkvh[(size_t)QKVD * DIM];
__device__ __half g_wouth[(size_t)DIM * DIM];
__device__ __half g_wfc1h[(size_t)HID * DIM];
__device__ __half g_wfc2h[(size_t)DIM * HID];

// ---------------------------------------------------------------------------
// Helpers
// ---------------------------------------------------------------------------
__device__ __forceinline__ uint32_t smem_u32(const void* p) {
    uint32_t a;
    asm("{ .reg .u64 t; cvta.to.shared.u64 t, %1; cvt.u32.u64 %0, t; }" : "=r"(a) : "l"(p));
    return a;
}
__device__ __forceinline__ void ldsm4(uint32_t* r, uint32_t addr) {
    asm volatile("ldmatrix.sync.aligned.m8n8.x4.shared.b16 {%0,%1,%2,%3}, [%4];"
        : "=r"(r[0]), "=r"(r[1]), "=r"(r[2]), "=r"(r[3]) : "r"(addr));
}
__device__ __forceinline__ void ldsm4t(uint32_t* r, uint32_t addr) {
    asm volatile("ldmatrix.sync.aligned.m8n8.x4.trans.shared.b16 {%0,%1,%2,%3}, [%4];"
        : "=r"(r[0]), "=r"(r[1]), "=r"(r[2]), "=r"(r[3]) : "r"(addr));
}
__device__ __forceinline__ void mma_f16(float* c, const uint32_t* a,
                                        uint32_t b0, uint32_t b1) {
    asm volatile(
        "mma.sync.aligned.m16n8k16.row.col.f32.f16.f16.f32 "
        "{%0,%1,%2,%3}, {%4,%5,%6,%7}, {%8,%9}, {%0,%1,%2,%3};"
        : "+f"(c[0]), "+f"(c[1]), "+f"(c[2]), "+f"(c[3])
        : "r"(a[0]), "r"(a[1]), "r"(a[2]), "r"(a[3]), "r"(b0), "r"(b1));
}
__device__ __forceinline__ uint32_t sw128(uint32_t off) {
    return off ^ ((off >> 3) & 0x70);
}
#define CP_ASYNC16(dst, src) \
    asm volatile("cp.async.cg.shared.global [%0], [%1], 16;" \
                 :: "r"(dst), "l"(src) : "memory")
#define CP_COMMIT() asm volatile("cp.async.commit_group;" ::: "memory")
#define CP_WAIT1()  asm volatile("cp.async.wait_group 1;"  ::: "memory")

// ---------------------------------------------------------------------------
// fp32 -> fp16 conversion, all four weights in one launch
// ---------------------------------------------------------------------------
__global__ void f2h_all_kernel(const float* __restrict__ s0, __half* __restrict__ d0, int n0,
                               const float* __restrict__ s1, __half* __restrict__ d1, int n1,
                               const float* __restrict__ s2, __half* __restrict__ d2, int n2,
                               const float* __restrict__ s3, __half* __restrict__ d3, int n3)
{
    int i = (blockIdx.x * 256 + threadIdx.x) * 4;
    const float* s; __half* d;
    if (i < n0)                   { s = s0; d = d0; }
    else if ((i -= n0) < n1)      { s = s1; d = d1; }
    else if ((i -= n1) < n2)      { s = s2; d = d2; }
    else if ((i -= n2) < n3)      { s = s3; d = d3; }
    else return;
    float4 v = *(const float4*)(s + i);
    *(__half2*)(d + i)     = __floats2half2_rn(v.x, v.y);
    *(__half2*)(d + i + 2) = __floats2half2_rn(v.z, v.w);
}

// ---------------------------------------------------------------------------
// LayerNorm: one block per row (D=768), 192 threads x float4, half out
// ---------------------------------------------------------------------------
__global__ void __launch_bounds__(192)
ln_kernel(const float* __restrict__ x,
          const float* __restrict__ gg,
          const float* __restrict__ bb,
          __half* __restrict__ y)
{
    const int row = blockIdx.x;
    const int tid = threadIdx.x;

    const float4 v = *(const float4*)(x + (size_t)row * DIM + tid * 4);
    float s = v.x + v.y + v.z + v.w;
    float q = v.x*v.x + v.y*v.y + v.z*v.z + v.w*v.w;

    #pragma unroll
    for (int m = 16; m; m >>= 1) {
        s += __shfl_xor_sync(0xffffffffu, s, m);
        q += __shfl_xor_sync(0xffffffffu, q, m);
    }
    __shared__ float sh[12];
    const int warp = tid >> 5, lane = tid & 31;
    if (!lane) { sh[warp] = s; sh[warp + 6] = q; }
    __syncthreads();
    if (tid == 0) {
        float ts = 0.f, tq = 0.f;
        #pragma unroll
        for (int w = 0; w < 6; w++) { ts += sh[w]; tq += sh[w + 6]; }
        sh[0] = ts * (1.0f / DIM);
        sh[6] = tq * (1.0f / DIM);
    }
    __syncthreads();
    const float mean = sh[0];
    const float rstd = rsqrtf(sh[6] - mean * mean + 1e-5f);

    const float4 g4 = *(const float4*)(gg + tid * 4);
    const float4 b4 = *(const float4*)(bb + tid * 4);
    __half2 h0 = __floats2half2_rn((v.x - mean) * rstd * g4.x + b4.x,
                                   (v.y - mean) * rstd * g4.y + b4.y);
    __half2 h1 = __floats2half2_rn((v.z - mean) * rstd * g4.z + b4.z,
                                   (v.w - mean) * rstd * g4.w + b4.w);
    *(__half2*)(y + (size_t)row * DIM + tid * 4)     = h0;
    *(__half2*)(y + (size_t)row * DIM + tid * 4 + 2) = h1;
}

// ---------------------------------------------------------------------------
// fp16 mma.sync GEMM, cp.async 3-stage pipeline (unchanged from R6).
// ---------------------------------------------------------------------------
template<int EPI, bool HALF_OUT>
__global__ void __launch_bounds__(256, 2)
tgemm_kernel(const __half* __restrict__ A,
             const __half* __restrict__ W,
             const float* __restrict__ bias,
             const float* __restrict__ res,
             void* __restrict__ Cv,
             int M, int N, int K)
{
    extern __shared__ char smem[];
    const uint32_t sb = smem_u32(smem);
    const int tid   = threadIdx.x;
    const int wid   = tid >> 5;
    const int lane  = tid & 31;
    const int warpM = wid & 3;
    const int warpN = wid >> 2;
    const int m0 = blockIdx.y * 128;
    const int n0 = blockIdx.x * 128;

    uint32_t aOff[2], bOff[4];
    {
        const int r8 = (lane & 7) + ((lane >> 3) & 1) * 8;
        #pragma unroll
        for (int mf = 0; mf < 2; mf++) {
            const int row = warpM * 32 + mf * 16 + r8;
            aOff[mf] = sw128((uint32_t)(row * 128 + (lane >> 4) * 16));
        }
        const int rB = (lane & 7) + ((lane >> 4) & 1) * 8;
        #pragma unroll
        for (int p = 0; p < 4; p++) {
            const int row = warpN * 64 + p * 16 + rB;
            bOff[p] = sw128((uint32_t)(row * 128 + ((lane >> 3) & 1) * 16));
        }
    }

    float acc[2][8][4];
    #pragma unroll
    for (int i = 0; i < 2; i++)
        #pragma unroll
        for (int j = 0; j < 8; j++)
            #pragma unroll
            for (int q = 0; q < 4; q++) acc[i][j][q] = 0.f;

    const int nIter = K >> 6;                 // BK = 64 halfs
    const int lrow  = tid >> 3;
    const int lch   = tid & 7;
    const uint32_t stOff = sw128((uint32_t)(lrow * 128 + lch * 16));
    const __half* apt = A + (size_t)(m0 + lrow) * K + lch * 8;
    const __half* bpt = W + (size_t)(n0 + lrow) * K + lch * 8;

    #pragma unroll
    for (int s = 0; s < 2; s++) {
        const int k0 = s << 6;
        const uint32_t dstA = sb + (uint32_t)s * 32768u + stOff;
        #pragma unroll
        for (int g = 0; g < 4; g++)
            CP_ASYNC16(dstA + g * 4096, apt + (size_t)g * 32 * K + k0);
        #pragma unroll
        for (int g = 0; g < 4; g++)
            CP_ASYNC16(dstA + 16384 + g * 4096, bpt + (size_t)g * 32 * K + k0);
        CP_COMMIT();
    }

    int slotNext = 2;
    for (int it = 0; it < nIter; ++it) {
        CP_WAIT1();
        __syncthreads();

        if (it + 2 < nIter) {
            const int k0 = (it + 2) << 6;
            const uint32_t dstA = sb + (uint32_t)slotNext * 32768u + stOff;
            #pragma unroll
            for (int g = 0; g < 4; g++)
                CP_ASYNC16(dstA + g * 4096, apt + (size_t)g * 32 * K + k0);
            #pragma unroll
            for (int g = 0; g < 4; g++)
                CP_ASYNC16(dstA + 16384 + g * 4096, bpt + (size_t)g * 32 * K + k0);
        }
        CP_COMMIT();
        slotNext = (slotNext == 2) ? 0 : slotNext + 1;

        const uint32_t aB = sb + (uint32_t)(it % 3) * 32768u;
        const uint32_t bB = aB + 16384u;

        #pragma unroll
        for (int ks = 0; ks < 4; ks++) {
            const uint32_t kx = (uint32_t)(ks << 5);
            uint32_t af[2][4], bf[4][4];
            #pragma unroll
            for (int mf = 0; mf < 2; mf++) ldsm4(af[mf], aB + (aOff[mf] ^ kx));
            #pragma unroll
            for (int p = 0; p < 4; p++)   ldsm4(bf[p],  bB + (bOff[p]  ^ kx));
            #pragma unroll
            for (int mf = 0; mf < 2; mf++)
                #pragma unroll
                for (int nf = 0; nf < 8; nf++)
                    mma_f16(acc[mf][nf], af[mf],
                            bf[nf >> 1][(nf & 1) * 2],
                            bf[nf >> 1][(nf & 1) * 2 + 1]);
        }
    }

    #pragma unroll
    for (int mf = 0; mf < 2; mf++) {
        const int r0 = m0 + warpM * 32 + mf * 16 + (lane >> 2);
        #pragma unroll
        for (int nf = 0; nf < 8; nf++) {
            const int col = n0 + warpN * 64 + nf * 8 + (lane & 3) * 2;
            const float b0 = bias[col], b1 = bias[col + 1];
            #pragma unroll
            for (int h = 0; h < 2; h++) {
                const int r = r0 + h * 8;
                float v0 = acc[mf][nf][h * 2 + 0] + b0;
                float v1 = acc[mf][nf][h * 2 + 1] + b1;
                if (EPI == 1) {
                    v0 = 0.5f * v0 * (1.0f + erff(v0 * 0.70710678118654752f));
                    v1 = 0.5f * v1 * (1.0f + erff(v1 * 0.70710678118654752f));
                }
                if (EPI == 2) {
                    const float2 rr = *(const float2*)(res + (size_t)r * N + col);
                    v0 += rr.x; v1 += rr.y;
                }
                if (HALF_OUT) {
                    *(__half2*)((__half*)Cv + (size_t)r * N + col) =
                        __floats2half2_rn(v0, v1);
                } else {
                    *(float2*)((float*)Cv + (size_t)r * N + col) =
                        make_float2(v0, v1);
                }
            }
        }
    }
}

// ---------------------------------------------------------------------------
// fp16 tensor-core flash attention, cp.async double-buffered K/V.
// Block: 128 q-rows x (head, batch). 8 warps x 16 q-rows. KV tiles of 64.
// SMEM: Q 16K @0 | K 2x8K @16384 | V 2x8K @32768 | P 16K @49152 = 64KB
// ---------------------------------------------------------------------------
__global__ void __launch_bounds__(256, 2)
attn_kernel(const __half* __restrict__ qkv, __half* __restrict__ out)
{
    extern __shared__ char smem[];
    const uint32_t sb = smem_u32(smem);
    const uint32_t Q0 = 0u, K0 = 16384u, V0 = 32768u, P0 = 49152u;

    const int b  = blockIdx.z;
    const int h  = blockIdx.y;
    const int q0 = blockIdx.x * 128;
    const int tid = threadIdx.x, wid = tid >> 5, lane = tid & 31;

    const float scale = 0.03608439182435161f;   // 1/sqrt(768)

    // KV loader coords: 2 uint4 each for K and V per thread
    const int krow = tid >> 3;               // 0..31 (+g*32)
    const int kch  = tid & 7;
    const uint32_t kvOff[2] = {
        sw128((uint32_t)(krow * 128 + kch * 16)),
        sw128((uint32_t)((krow + 32) * 128 + kch * 16))
    };

    // ---- load Q tile 128x64 (raw halves, 128B rows, sw128) ----
    #pragma unroll
    for (int g = 0; g < 4; g++) {
        const int idx = tid + g * 256;
        const int row = idx >> 3, ch = idx & 7;
        const __half* qp = qkv + (size_t)(b * SEQ + q0 + row) * QKVD + h * HDIM + ch * 8;
        *(uint4*)(smem + Q0 + sw128((uint32_t)(row * 128 + ch * 16))) =
            *(const uint4*)qp;
    }

    // ---- prefetch KV tile 0 into buffer 0 ----
    {
        const __half* kp = qkv + (size_t)(b * SEQ + krow) * QKVD + DIM + h * HDIM + kch * 8;
        #pragma unroll
        for (int g = 0; g < 2; g++) {
            const __half* src = kp + (size_t)g * 32 * QKVD;
            CP_ASYNC16(sb + K0 + kvOff[g], src);
            CP_ASYNC16(sb + V0 + kvOff[g], src + DIM);
        }
        CP_COMMIT();
    }

    // ---- fragment offsets ----
    uint32_t aOffQ, bOffK[4], bOffV[4];
    {
        const int r8 = (lane & 7) + ((lane >> 3) & 1) * 8;
        aOffQ = sw128((uint32_t)((wid * 16 + r8) * 128 + (lane >> 4) * 16));
        const int rB = (lane & 7) + ((lane >> 4) & 1) * 8;
        #pragma unroll
        for (int p = 0; p < 4; p++)
            bOffK[p] = sw128((uint32_t)((p * 16 + rB) * 128 + ((lane >> 3) & 1) * 16));
        #pragma unroll
        for (int p = 0; p < 4; p++)
            bOffV[p] = sw128((uint32_t)(r8 * 128 + p * 32 + ((lane >> 4) & 1) * 16));
    }
    const uint32_t aOffP = aOffQ;

    float accO[8][4];
    #pragma unroll
    for (int j = 0; j < 8; j++)
        #pragma unroll
        for (int q = 0; q < 4; q++) accO[j][q] = 0.f;
    float m_i[2] = {-1e30f, -1e30f}, l_i[2] = {0.f, 0.f};

    const int pr = wid * 16 + (lane >> 2);
    const uint32_t xrp = ((uint32_t)(pr & 7)) << 4;
    const uint32_t pcb = (uint32_t)((lane & 3) * 4);

    for (int t = 0; t < SEQ / 64; t++) {
        // issue prefetch for tile t+1 (end-of-iter barrier makes buffer safe)
        if (t + 1 < SEQ / 64) {
            const uint32_t buf = (uint32_t)((t + 1) & 1) * 8192u;
            const __half* kp = qkv + (size_t)(b * SEQ + (t + 1) * 64 + krow) * QKVD
                               + DIM + h * HDIM + kch * 8;
            #pragma unroll
            for (int g = 0; g < 2; g++) {
                const __half* src = kp + (size_t)g * 32 * QKVD;
                CP_ASYNC16(sb + K0 + buf + kvOff[g], src);
                CP_ASYNC16(sb + V0 + buf + kvOff[g], src + DIM);
            }
        }
        CP_COMMIT();
        CP_WAIT1();            // tile t resident
        __syncthreads();       // visible to all warps

        const uint32_t kB = sb + K0 + (uint32_t)(t & 1) * 8192u;
        const uint32_t vB = sb + V0 + (uint32_t)(t & 1) * 8192u;

        // ---- S = Q K^T ----
        float accS[8][4];
        #pragma unroll
        for (int j = 0; j < 8; j++)
            #pragma unroll
            for (int q = 0; q < 4; q++) accS[j][q] = 0.f;

        #pragma unroll
        for (int ds = 0; ds < 4; ds++) {
            const uint32_t kx = (uint32_t)(ds << 5);
            uint32_t aq[4], bk[4][4];
            ldsm4(aq, sb + Q0 + (aOffQ ^ kx));
            #pragma unroll
            for (int p = 0; p < 4; p++)
                ldsm4(bk[p], kB + (bOffK[p] ^ kx));
            #pragma unroll
            for (int nf = 0; nf < 8; nf++)
                mma_f16(accS[nf], aq,
                        bk[nf >> 1][(nf & 1) * 2],
                        bk[nf >> 1][(nf & 1) * 2 + 1]);
        }
        #pragma unroll
        for (int nf = 0; nf < 8; nf++)
            #pragma unroll
            for (int q = 0; q < 4; q++) accS[nf][q] *= scale;

        // ---- online softmax ----
        float mx0 = -1e30f, mx1 = -1e30f;
        #pragma unroll
        for (int nf = 0; nf < 8; nf++) {
            mx0 = fmaxf(mx0, fmaxf(accS[nf][0], accS[nf][1]));
            mx1 = fmaxf(mx1, fmaxf(accS[nf][2], accS[nf][3]));
        }
        mx0 = fmaxf(mx0, __shfl_xor_sync(0xffffffffu, mx0, 1));
        mx0 = fmaxf(mx0, __shfl_xor_sync(0xffffffffu, mx0, 2));
        mx1 = fmaxf(mx1, __shfl_xor_sync(0xffffffffu, mx1, 1));
        mx1 = fmaxf(mx1, __shfl_xor_sync(0xffffffffu, mx1, 2));

        const float mn0 = fmaxf(m_i[0], mx0), mn1 = fmaxf(m_i[1], mx1);
        const float al0 = __expf(m_i[0] - mn0), al1 = __expf(m_i[1] - mn1);
        float s0 = 0.f, s1 = 0.f;
        #pragma unroll
        for (int nf = 0; nf < 8; nf++) {
            accS[nf][0] = __expf(accS[nf][0] - mn0); s0 += accS[nf][0];
            accS[nf][1] = __expf(accS[nf][1] - mn0); s0 += accS[nf][1];
            accS[nf][2] = __expf(accS[nf][2] - mn1); s1 += accS[nf][2];
            accS[nf][3] = __expf(accS[nf][3] - mn1); s1 += accS[nf][3];
        }
        s0 += __shfl_xor_sync(0xffffffffu, s0, 1);
        s0 += __shfl_xor_sync(0xffffffffu, s0, 2);
        s1 += __shfl_xor_sync(0xffffffffu, s1, 1);
        s1 += __shfl_xor_sync(0xffffffffu, s1, 2);
        l_i[0] = l_i[0] * al0 + s0;  m_i[0] = mn0;
        l_i[1] = l_i[1] * al1 + s1;  m_i[1] = mn1;
        #pragma unroll
        for (int nf = 0; nf < 8; nf++) {
            accO[nf][0] *= al0; accO[nf][1] *= al0;
            accO[nf][2] *= al1; accO[nf][3] *= al1;
        }

        // ---- store P as half2 (warp-private rows) ----
        #pragma unroll
        for (int nf = 0; nf < 8; nf++) {
            const uint32_t cb = (uint32_t)(nf * 16) + pcb;
            *(__half2*)(smem + P0 + (uint32_t)(pr * 128) + (cb ^ xrp)) =
                __floats2half2_rn(accS[nf][0], accS[nf][1]);
            *(__half2*)(smem + P0 + (uint32_t)((pr + 8) * 128) + (cb ^ xrp)) =
                __floats2half2_rn(accS[nf][2], accS[nf][3]);
        }
        __syncwarp();

        // ---- O += P V ----
        #pragma unroll
        for (int ks = 0; ks < 4; ks++) {
            uint32_t ap[4], bv[4][4];
            ldsm4(ap, sb + P0 + (aOffP ^ ((uint32_t)(ks << 5))));
            #pragma unroll
            for (int p = 0; p < 4; p++)
                ldsm4t(bv[p], vB + bOffV[p] + (uint32_t)(ks * 2048));
            #pragma unroll
            for (int nf = 0; nf < 8; nf++)
                mma_f16(accO[nf], ap,
                        bv[nf >> 1][(nf & 1) * 2],
                        bv[nf >> 1][(nf & 1) * 2 + 1]);
        }
        __syncthreads();   // compute done before next iter's prefetch overwrites
    }

    // ---- normalize + store (half) ----
    {
        const int r0 = wid * 16 + (lane >> 2);
        #pragma unroll
        for (int half = 0; half < 2; half++) {
            const int r = r0 + half * 8;
            const float inv = 1.0f / l_i[half];
            __half* op = out + (size_t)(b * SEQ + q0 + r) * DIM + h * HDIM;
            #pragma unroll
            for (int nf = 0; nf < 8; nf++)
                *(__half2*)(op + nf * 8 + (lane & 3) * 2) =
                    __floats2half2_rn(accO[nf][half * 2] * inv,
                                      accO[nf][half * 2 + 1] * inv);
        }
    }
}

// ---------------------------------------------------------------------------
// Host entry
// ---------------------------------------------------------------------------
extern "C" void kernel_launch(void* const* d_in, const int* in_sizes, int n_in,
                              void* d_out, int out_size)
{
    const float* x     = (const float*)d_in[0];
    const float* ln_g  = (const float*)d_in[1];
    const float* ln_b  = (const float*)d_in[2];
    const float* w_qkv = (const float*)d_in[3];
    const float* b_qkv = (const float*)d_in[4];
    const float* w_out = (const float*)d_in[5];
    const float* b_out = (const float*)d_in[6];
    const float* w_fc1 = (const float*)d_in[7];
    const float* b_fc1 = (const float*)d_in[8];
    const float* w_fc2 = (const float*)d_in[9];
    const float* b_fc2 = (const float*)d_in[10];
    float* out = (float*)d_out;

    __half *p_lnh, *p_qkvh, *p_atth, *p_hh;
    __half *p_wqkv, *p_wout, *p_wfc1, *p_wfc2;
    float  *p_x1;
    cudaGetSymbolAddress((void**)&p_lnh,  g_lnh);
    cudaGetSymbolAddress((void**)&p_qkvh, g_qkvh);
    cudaGetSymbolAddress((void**)&p_atth, g_atth);
    cudaGetSymbolAddress((void**)&p_hh,   g_hh);
    cudaGetSymbolAddress((void**)&p_x1,   g_x1);
    cudaGetSymbolAddress((void**)&p_wqkv, g_wqkvh);
    cudaGetSymbolAddress((void**)&p_wout, g_wouth);
    cudaGetSymbolAddress((void**)&p_wfc1, g_wfc1h);
    cudaGetSymbolAddress((void**)&p_wfc2, g_wfc2h);

    const int SMEM_G = 98304;   // GEMM: 3 stages x 32KB
    const int SMEM_A = 65536;   // attn: Q16 + K16 + V16 + P16
    cudaFuncSetAttribute(tgemm_kernel<0, true>,
        cudaFuncAttributeMaxDynamicSharedMemorySize, SMEM_G);
    cudaFuncSetAttribute(tgemm_kernel<1, true>,
        cudaFuncAttributeMaxDynamicSharedMemorySize, SMEM_G);
    cudaFuncSetAttribute(tgemm_kernel<2, false>,
        cudaFuncAttributeMaxDynamicSharedMemorySize, SMEM_G);
    cudaFuncSetAttribute(attn_kernel,
        cudaFuncAttributeMaxDynamicSharedMemorySize, SMEM_A);

    // 0) convert all weights to fp16 (single launch)
    const int n0 = QKVD * DIM, n1 = DIM * DIM, n2 = HID * DIM, n3 = DIM * HID;
    const int nAll = n0 + n1 + n2 + n3;
    f2h_all_kernel<<<(nAll / 4 + 255) / 256, 256>>>(
        w_qkv, p_wqkv, n0, w_out, p_wout, n1,
        w_fc1, p_wfc1, n2, w_fc2, p_wfc2, n3);

    // 1) ln1 = LN(x) -> half
    ln_kernel<<<ROWS, 192>>>(x, ln_g, ln_b, p_lnh);

    // 2) qkv = ln1 @ w_qkv^T + b_qkv -> half
    tgemm_kernel<0, true><<<dim3(QKVD / 128, ROWS / 128), 256, SMEM_G>>>(
        p_lnh, p_wqkv, b_qkv, nullptr, p_qkvh, ROWS, QKVD, DIM);

    // 3) fused attention -> half
    attn_kernel<<<dim3(SEQ / 128, HEADS, BATCH), 256, SMEM_A>>>(p_qkvh, p_atth);

    // 4) x1 = x + att @ w_out^T + b_out  (fp32)
    tgemm_kernel<2, false><<<dim3(DIM / 128, ROWS / 128), 256, SMEM_G>>>(
        p_atth, p_wout, b_out, x, p_x1, ROWS, DIM, DIM);

    // 5) ln2 = LN(x1) -> half
    ln_kernel<<<ROWS, 192>>>(p_x1, ln_g, ln_b, p_lnh);

    // 6) h = gelu(ln2 @ w_fc1^T + b_fc1) -> half
    tgemm_kernel<1, true><<<dim3(HID / 128, ROWS / 128), 256, SMEM_G>>>(
        p_lnh, p_wfc1, b_fc1, nullptr, p_hh, ROWS, HID, DIM);

    // 7) out = x1 + h @ w_fc2^T + b_fc2  (fp32)
    tgemm_kernel<2, false><<<dim3(DIM / 128, ROWS / 128), 256, SMEM_G>>>(
        p_hh, p_wfc2, b_fc2, p_x1, out, ROWS, DIM, HID);
}